// round 8
// baseline (speedup 1.0000x reference)
#include <cuda_runtime.h>
#include <cuda_bf16.h>
#include <cstdint>

#define DM     1024
#define NH     16
#define DH     64
#define SEQ    2048
#define BATCH  2
#define M_TOT  (BATCH * SEQ)   // 4096

// ---- pre-split bf16 scratch (hi/lo pairs) ----
__device__ __nv_bfloat16 g_xh[(size_t)M_TOT * DM], g_xl[(size_t)M_TOT * DM];
__device__ __nv_bfloat16 g_sh[(size_t)M_TOT * DM], g_sl[(size_t)M_TOT * DM];
__device__ __nv_bfloat16 g_qh[(size_t)M_TOT * DM], g_ql[(size_t)M_TOT * DM];
__device__ __nv_bfloat16 g_kh[(size_t)M_TOT * DM], g_kl[(size_t)M_TOT * DM];
__device__ __nv_bfloat16 g_vh[(size_t)M_TOT * DM], g_vl[(size_t)M_TOT * DM];
__device__ __nv_bfloat16 g_oh[(size_t)M_TOT * DM], g_ol[(size_t)M_TOT * DM];
__device__ __nv_bfloat16 g_wqh[DM * DM], g_wql[DM * DM];
__device__ __nv_bfloat16 g_wkh[DM * DM], g_wkl[DM * DM];
__device__ __nv_bfloat16 g_wvh[DM * DM], g_wvl[DM * DM];
__device__ __nv_bfloat16 g_woh[DM * DM], g_wol[DM * DM];

// ===========================================================================
// Helpers
// ===========================================================================
__device__ __forceinline__ uint32_t smem_u32(const void* p) {
    uint32_t a;
    asm("{ .reg .u64 t; cvta.to.shared.u64 t, %1; cvt.u32.u64 %0, t; }"
        : "=r"(a) : "l"(p));
    return a;
}
__device__ __forceinline__ void ldsm4(uint32_t* r, uint32_t addr) {
    asm volatile("ldmatrix.sync.aligned.m8n8.x4.shared.b16 {%0,%1,%2,%3}, [%4];"
                 : "=r"(r[0]), "=r"(r[1]), "=r"(r[2]), "=r"(r[3]) : "r"(addr));
}
__device__ __forceinline__ void ldsm4t(uint32_t* r, uint32_t addr) {
    asm volatile("ldmatrix.sync.aligned.m8n8.x4.trans.shared.b16 {%0,%1,%2,%3}, [%4];"
                 : "=r"(r[0]), "=r"(r[1]), "=r"(r[2]), "=r"(r[3]) : "r"(addr));
}
__device__ __forceinline__ void cpa16(uint32_t saddr, const void* gaddr) {
    asm volatile("cp.async.cg.shared.global [%0], [%1], 16;"
                 :: "r"(saddr), "l"(gaddr) : "memory");
}
#define CP_COMMIT asm volatile("cp.async.commit_group;" ::: "memory")
#define CP_WAIT0  asm volatile("cp.async.wait_group 0;" ::: "memory")
#define CP_WAIT1  asm volatile("cp.async.wait_group 1;" ::: "memory")

#define MMA_BF16(d, a, b0, b1) \
    asm volatile("mma.sync.aligned.m16n8k16.row.col.f32.bf16.bf16.f32 " \
                 "{%0,%1,%2,%3},{%4,%5,%6,%7},{%8,%9},{%0,%1,%2,%3};" \
                 : "+f"((d)[0]), "+f"((d)[1]), "+f"((d)[2]), "+f"((d)[3]) \
                 : "r"((a)[0]), "r"((a)[1]), "r"((a)[2]), "r"((a)[3]), \
                   "r"(b0), "r"(b1))

__device__ __forceinline__ float trunc_hi(float x) {
    return __uint_as_float(__float_as_uint(x) & 0xFFFF0000u);
}
__device__ __forceinline__ uint32_t pack_hi2(float x, float y) {
    return (__float_as_uint(y) & 0xFFFF0000u) | (__float_as_uint(x) >> 16);
}
__device__ __forceinline__ uint32_t pack_rn2(float x, float y) {
    __nv_bfloat162 p = __floats2bfloat162_rn(x, y);
    return *reinterpret_cast<uint32_t*>(&p);
}
__device__ __forceinline__ float fexp2(float x) {
    x = fmaxf(x, -126.0f);
    float z = x + 12582912.0f;
    float f = x - (z - 12582912.0f);
    float p = 0.0013333558f;
    p = fmaf(p, f, 0.0096181291f);
    p = fmaf(p, f, 0.0555041087f);
    p = fmaf(p, f, 0.2402265069f);
    p = fmaf(p, f, 0.6931471806f);
    p = fmaf(p, f, 1.0f);
    return __uint_as_float(__float_as_uint(p) + (__float_as_uint(z) << 23));
}

// ===========================================================================
// Prep: fp32 -> (hi, lo) bf16 split, optional scale. 4 floats/thread.
// ===========================================================================
__global__ __launch_bounds__(256) void prep_split(const float4* __restrict__ in,
                                                  uint2* __restrict__ hi,
                                                  uint2* __restrict__ lo,
                                                  int n4, float scale) {
    int i = blockIdx.x * blockDim.x + threadIdx.x;
    if (i >= n4) return;
    float4 v = in[i];
    v.x *= scale; v.y *= scale; v.z *= scale; v.w *= scale;
    hi[i] = make_uint2(pack_hi2(v.x, v.y), pack_hi2(v.z, v.w));
    lo[i] = make_uint2(pack_rn2(v.x - trunc_hi(v.x), v.y - trunc_hi(v.y)),
                       pack_rn2(v.z - trunc_hi(v.z), v.w - trunc_hi(v.w)));
}

// ===========================================================================
// Pure bf16 split GEMM core: Y = A @ B^T from pre-split hi/lo bf16 arrays.
// 128x128 CTA tile, KC=32, cp.async double-buffer, 2 CTAs/SM.
// ===========================================================================
#define KC   32
#define LDT  40                          // bf16 per smem row (padded, 80B)
#define TILE_BYTES (128 * LDT * 2)       // 10240
#define STAGE_BYTES (4 * TILE_BYTES)     // Ahi, Alo, Bhi, Blo
#define GSMEM (2 * STAGE_BYTES)          // 81920

__device__ __forceinline__ void g_issue(uint32_t ss, const char* Ah,
                                        const char* Al, const char* Bh,
                                        const char* Bl, int m0, int n0,
                                        uint32_t k0b, int t) {
#pragma unroll
    for (int i = 0; i < 8; i++) {
        const char* g = (i < 2) ? Ah : (i < 4) ? Al : (i < 6) ? Bh : Bl;
        const int r0  = (i < 4) ? m0 : n0;
        const int row = ((i & 1) << 6) + (t >> 2);
        const uint32_t c16 = (uint32_t)(t & 3) << 4;
        cpa16(ss + (uint32_t)(i >> 1) * (uint32_t)TILE_BYTES
                 + (uint32_t)row * 80u + c16,
              g + (size_t)(r0 + row) * 2048 + k0b + c16);
    }
}

__device__ __forceinline__ void gemm_core(const char* Ah, const char* Al,
                                          const char* Bh, const char* Bl,
                                          uint32_t sbase, int m0, int n0,
                                          float (&acc)[4][4][4]) {
    const int t    = threadIdx.x;
    const int lane = t & 31;
    const int wid  = t >> 5;
    const int wm   = wid & 1;
    const int wn   = wid >> 1;

#pragma unroll
    for (int mi = 0; mi < 4; mi++)
#pragma unroll
        for (int ni = 0; ni < 4; ni++)
#pragma unroll
            for (int e = 0; e < 4; e++) acc[mi][ni][e] = 0.f;

    const int r8  = lane & 7;
    const int sel = lane >> 3;
    const uint32_t aRowOff = (uint32_t)(wm * 64 + (sel & 1) * 8 + r8) * (LDT * 2);
    const uint32_t aKOff   = (uint32_t)((sel >> 1) * 8) * 2;
    const uint32_t bRowBase = (uint32_t)(wn * 32 + (sel >> 1) * 8 + r8) * (LDT * 2);
    const uint32_t bKOff    = (uint32_t)((sel & 1) * 8) * 2;

    auto compute = [&](uint32_t sb) {
#pragma unroll
        for (int ks = 0; ks < 2; ks++) {
            const uint32_t kb = (uint32_t)ks * 32;
#pragma unroll
            for (int c = 0; c < 3; c++) {
                const uint32_t abase = sb + (c == 2 ? TILE_BYTES : 0u);
                const uint32_t bbase = sb + 2 * TILE_BYTES + (c == 1 ? TILE_BYTES : 0u);
                uint32_t afr[4][4];
#pragma unroll
                for (int mi = 0; mi < 4; mi++)
                    ldsm4(afr[mi], abase + aRowOff
                                 + (uint32_t)(mi * 16) * (LDT * 2) + kb + aKOff);
                uint32_t bfr[2][4];
#pragma unroll
                for (int np = 0; np < 2; np++)
                    ldsm4(bfr[np], bbase + bRowBase
                                 + (uint32_t)(np * 16) * (LDT * 2) + kb + bKOff);
#pragma unroll
                for (int mi = 0; mi < 4; mi++)
#pragma unroll
                    for (int ni = 0; ni < 4; ni++)
                        MMA_BF16(acc[mi][ni], afr[mi],
                                 bfr[ni >> 1][(ni & 1) * 2],
                                 bfr[ni >> 1][(ni & 1) * 2 + 1]);
            }
        }
    };

    g_issue(sbase, Ah, Al, Bh, Bl, m0, n0, 0u, t);
    CP_COMMIT;

    const int NCHUNK = DM / KC;   // 32
    for (int chunk = 0; chunk < NCHUNK; chunk++) {
        const int s = chunk & 1;
        CP_WAIT0;
        __syncthreads();
        if (chunk + 1 < NCHUNK) {
            g_issue(sbase + (uint32_t)(s ^ 1) * STAGE_BYTES, Ah, Al, Bh, Bl,
                    m0, n0, (uint32_t)(chunk + 1) * KC * 2, t);
            CP_COMMIT;
        }
        compute(sbase + (uint32_t)s * STAGE_BYTES);
    }
}

// QKV projections: z selects (A, B, Y). Epilogue writes hi/lo bf16.
__global__ __launch_bounds__(256, 2)
void gemm_qkv2(const char* xh, const char* xl, const char* sh, const char* sl,
               const char* wqh, const char* wql, const char* wkh, const char* wkl,
               const char* wvh, const char* wvl,
               uint32_t* qh, uint32_t* ql, uint32_t* kh, uint32_t* kl,
               uint32_t* vh, uint32_t* vl) {
    extern __shared__ __align__(16) char sm[];
    const int z  = blockIdx.z;
    const int m0 = blockIdx.y * 128;
    const int n0 = blockIdx.x * 128;
    const char* Ah = (z == 0) ? xh : sh;
    const char* Al = (z == 0) ? xl : sl;
    const char* Bh = (z == 0) ? wqh : (z == 1 ? wkh : wvh);
    const char* Bl = (z == 0) ? wql : (z == 1 ? wkl : wvl);
    uint32_t* Yh   = (z == 0) ? qh : (z == 1 ? kh : vh);
    uint32_t* Yl   = (z == 0) ? ql : (z == 1 ? kl : vl);

    float acc[4][4][4];
    gemm_core(Ah, Al, Bh, Bl, smem_u32(sm), m0, n0, acc);

    const int lane = threadIdx.x & 31;
    const int wid  = threadIdx.x >> 5;
    const int wm   = wid & 1, wn = wid >> 1;
    const int g  = lane >> 2;
    const int c2 = (lane & 3) * 2;
#pragma unroll
    for (int mi = 0; mi < 4; mi++) {
#pragma unroll
        for (int ni = 0; ni < 4; ni++) {
            int row = m0 + wm * 64 + mi * 16 + g;
            int col = n0 + wn * 32 + ni * 8 + c2;
            size_t i0 = ((size_t)row * DM + col) >> 1;
            size_t i1 = ((size_t)(row + 8) * DM + col) >> 1;
            float a0 = acc[mi][ni][0], a1 = acc[mi][ni][1];
            float a2 = acc[mi][ni][2], a3 = acc[mi][ni][3];
            Yh[i0] = pack_hi2(a0, a1);
            Yl[i0] = pack_rn2(a0 - trunc_hi(a0), a1 - trunc_hi(a1));
            Yh[i1] = pack_hi2(a2, a3);
            Yl[i1] = pack_rn2(a2 - trunc_hi(a2), a3 - trunc_hi(a3));
        }
    }
}

// Output projection: fp32 epilogue to d_out.
__global__ __launch_bounds__(256, 2)
void gemm_out2(const char* oh, const char* ol, const char* wh, const char* wl,
               float* __restrict__ Y) {
    extern __shared__ __align__(16) char sm[];
    const int m0 = blockIdx.y * 128;
    const int n0 = blockIdx.x * 128;

    float acc[4][4][4];
    gemm_core(oh, ol, wh, wl, smem_u32(sm), m0, n0, acc);

    const int lane = threadIdx.x & 31;
    const int wid  = threadIdx.x >> 5;
    const int wm   = wid & 1, wn = wid >> 1;
    const int g  = lane >> 2;
    const int c2 = (lane & 3) * 2;
#pragma unroll
    for (int mi = 0; mi < 4; mi++) {
#pragma unroll
        for (int ni = 0; ni < 4; ni++) {
            int row = m0 + wm * 64 + mi * 16 + g;
            int col = n0 + wn * 32 + ni * 8 + c2;
            float2 v0 = {acc[mi][ni][0], acc[mi][ni][1]};
            float2 v1 = {acc[mi][ni][2], acc[mi][ni][3]};
            *(float2*)(Y + (size_t)row * DM + col)       = v0;
            *(float2*)(Y + (size_t)(row + 8) * DM + col) = v1;
        }
    }
}

// ===========================================================================
// Flash attention v5: pre-split inputs via cp.async, split K/V groups for
// load/compute overlap. 128 threads / 64 q-rows, 4 CTAs/SM.
// ===========================================================================
#define QROW_B 144
#define FT     9216                      // one 64-row tile (64*144)
#define FQHI   0
#define FQLO   (1 * FT)
#define FKHI   (2 * FT)
#define FKLO   (3 * FT)
#define FVHI   (4 * FT)
#define FVLO   (5 * FT)
#define FSMEM  (6 * FT)                  // 55296

__global__ __launch_bounds__(128, 4)
void flash_v5(const char* Qh, const char* Ql, const char* Kh, const char* Kl,
              const char* Vh, const char* Vl,
              uint32_t* Oh, uint32_t* Ol) {
    extern __shared__ __align__(16) char fsm[];
    const uint32_t sb = smem_u32(fsm);

    const int t    = threadIdx.x;
    const int lane = t & 31;
    const int wid  = t >> 5;            // 0..3
    const int b    = blockIdx.z;
    const int h    = blockIdx.y;
    const int q0   = blockIdx.x * 64;
    const size_t rq  = (size_t)(b * SEQ + q0);
    const size_t rb0 = (size_t)(b * SEQ);
    const uint32_t hoff = (uint32_t)h * 128u;

    const int rI  = t >> 3;             // 0..15 row sub-index
    const uint32_t c16 = (uint32_t)(t & 7) << 4;

    // ---- Q group + K(0) group ----
#pragma unroll
    for (int i = 0; i < 8; i++) {
        const char* g = (i < 4) ? Qh : Ql;
        const int row = ((i & 3) << 4) + rI;
        cpa16(sb + (uint32_t)(i >> 2) * FT + (uint32_t)row * QROW_B + c16,
              g + (rq + row) * 2048 + hoff + c16);
    }
#pragma unroll
    for (int i = 0; i < 8; i++) {
        const char* g = (i < 4) ? Kh : Kl;
        const int row = ((i & 3) << 4) + rI;
        cpa16(sb + FKHI + (uint32_t)(i >> 2) * FT + (uint32_t)row * QROW_B + c16,
              g + (rb0 + row) * 2048 + hoff + c16);
    }
    CP_COMMIT;
    // ---- V(0) group ----
#pragma unroll
    for (int i = 0; i < 8; i++) {
        const char* g = (i < 4) ? Vh : Vl;
        const int row = ((i & 3) << 4) + rI;
        cpa16(sb + FVHI + (uint32_t)(i >> 2) * FT + (uint32_t)row * QROW_B + c16,
              g + (rb0 + row) * 2048 + hoff + c16);
    }
    CP_COMMIT;

    const int r8  = lane & 7;
    const int sel = lane >> 3;
    const uint32_t aOff = (uint32_t)(wid * 16 + (sel & 1) * 8 + r8) * QROW_B
                        + (uint32_t)((sel >> 1) * 16);
    const uint32_t bOff = (uint32_t)((sel >> 1) * 8 + r8) * QROW_B
                        + (uint32_t)((sel & 1) * 16);
    const uint32_t vOff = (uint32_t)((sel & 1) * 8 + r8) * QROW_B
                        + (uint32_t)((sel >> 1) * 16);

    float m_s[2] = {-1.0e30f, -1.0e30f};
    float l_s[2] = {0.f, 0.f};
    float o[8][4];
#pragma unroll
    for (int j = 0; j < 8; j++)
#pragma unroll
        for (int e = 0; e < 4; e++) o[j][e] = 0.f;

    const int NT = SEQ / 64;   // 32
    for (int kt = 0; kt < NT; kt++) {
        const size_t rn = rb0 + (size_t)(kt + 1) * 64;
        const bool more = (kt + 1 < NT);

        CP_WAIT1;               // K(kt) (and Q on first iter) arrived
        __syncthreads();

        // ---- S = Q' @ K^T (split) ----
        float s[8][4];
#pragma unroll
        for (int j = 0; j < 8; j++)
#pragma unroll
            for (int e = 0; e < 4; e++) s[j][e] = 0.f;

#pragma unroll
        for (int kc = 0; kc < 4; kc++) {
            const uint32_t kb = (uint32_t)kc * 32;
            uint32_t ahi[4], alo[4];
            ldsm4(ahi, sb + FQHI + aOff + kb);
            ldsm4(alo, sb + FQLO + aOff + kb);
#pragma unroll
            for (int j = 0; j < 4; j++) {
                const uint32_t rowj = (uint32_t)(j * 16) * QROW_B;
                uint32_t bh[4], bl[4];
                ldsm4(bh, sb + FKHI + bOff + rowj + kb);
                ldsm4(bl, sb + FKLO + bOff + rowj + kb);
                MMA_BF16(s[2 * j],     ahi, bh[0], bh[1]);
                MMA_BF16(s[2 * j + 1], ahi, bh[2], bh[3]);
                MMA_BF16(s[2 * j],     ahi, bl[0], bl[1]);
                MMA_BF16(s[2 * j + 1], ahi, bl[2], bl[3]);
                MMA_BF16(s[2 * j],     alo, bh[0], bh[1]);
                MMA_BF16(s[2 * j + 1], alo, bh[2], bh[3]);
            }
        }

        __syncthreads();        // all warps done reading K(kt)
        if (more) {             // K(kt+1) loads during softmax + PV
#pragma unroll
            for (int i = 0; i < 8; i++) {
                const char* g = (i < 4) ? Kh : Kl;
                const int row = ((i & 3) << 4) + rI;
                cpa16(sb + FKHI + (uint32_t)(i >> 2) * FT
                         + (uint32_t)row * QROW_B + c16,
                      g + (rn + row) * 2048 + hoff + c16);
            }
            CP_COMMIT;
        }

        // ---- online softmax (log2 domain) ----
        float mx0 = s[0][0], mx1 = s[0][2];
#pragma unroll
        for (int j = 0; j < 8; j++) {
            mx0 = fmaxf(mx0, fmaxf(s[j][0], s[j][1]));
            mx1 = fmaxf(mx1, fmaxf(s[j][2], s[j][3]));
        }
        mx0 = fmaxf(mx0, __shfl_xor_sync(0xffffffffu, mx0, 1));
        mx0 = fmaxf(mx0, __shfl_xor_sync(0xffffffffu, mx0, 2));
        mx1 = fmaxf(mx1, __shfl_xor_sync(0xffffffffu, mx1, 1));
        mx1 = fmaxf(mx1, __shfl_xor_sync(0xffffffffu, mx1, 2));

        const float mn0 = fmaxf(m_s[0], mx0);
        const float mn1 = fmaxf(m_s[1], mx1);
        const float al0 = fexp2(m_s[0] - mn0);
        const float al1 = fexp2(m_s[1] - mn1);
        m_s[0] = mn0; m_s[1] = mn1;

        float sum0 = 0.f, sum1 = 0.f;
#pragma unroll
        for (int j = 0; j < 8; j++) {
            s[j][0] = fexp2(s[j][0] - mn0);
            s[j][1] = fexp2(s[j][1] - mn0);
            s[j][2] = fexp2(s[j][2] - mn1);
            s[j][3] = fexp2(s[j][3] - mn1);
            sum0 += s[j][0] + s[j][1];
            sum1 += s[j][2] + s[j][3];
        }
        sum0 += __shfl_xor_sync(0xffffffffu, sum0, 1);
        sum0 += __shfl_xor_sync(0xffffffffu, sum0, 2);
        sum1 += __shfl_xor_sync(0xffffffffu, sum1, 1);
        sum1 += __shfl_xor_sync(0xffffffffu, sum1, 2);
        l_s[0] = l_s[0] * al0 + sum0;
        l_s[1] = l_s[1] * al1 + sum1;

#pragma unroll
        for (int j = 0; j < 8; j++) {
            o[j][0] *= al0; o[j][1] *= al0;
            o[j][2] *= al1; o[j][3] *= al1;
        }

        if (more) { CP_WAIT1; } else { CP_WAIT0; }   // V(kt) arrived
        __syncthreads();

        // ---- P split hi/lo + PV (3-combo split) ----
#pragma unroll
        for (int kk = 0; kk < 4; kk++) {
            float* s0 = s[2 * kk];
            float* s1 = s[2 * kk + 1];
            uint32_t ph[4], pl[4];
            ph[0] = pack_hi2(s0[0], s0[1]);
            ph[1] = pack_hi2(s0[2], s0[3]);
            ph[2] = pack_hi2(s1[0], s1[1]);
            ph[3] = pack_hi2(s1[2], s1[3]);
            pl[0] = pack_rn2(s0[0] - trunc_hi(s0[0]), s0[1] - trunc_hi(s0[1]));
            pl[1] = pack_rn2(s0[2] - trunc_hi(s0[2]), s0[3] - trunc_hi(s0[3]));
            pl[2] = pack_rn2(s1[0] - trunc_hi(s1[0]), s1[1] - trunc_hi(s1[1]));
            pl[3] = pack_rn2(s1[2] - trunc_hi(s1[2]), s1[3] - trunc_hi(s1[3]));
            const uint32_t rowk = (uint32_t)(kk * 16) * QROW_B;
#pragma unroll
            for (int j = 0; j < 4; j++) {
                uint32_t vh[4], vl[4];
                ldsm4t(vh, sb + FVHI + vOff + rowk + (uint32_t)(j * 32));
                ldsm4t(vl, sb + FVLO + vOff + rowk + (uint32_t)(j * 32));
                MMA_BF16(o[2 * j],     ph, vh[0], vh[1]);
                MMA_BF16(o[2 * j + 1], ph, vh[2], vh[3]);
                MMA_BF16(o[2 * j],     ph, vl[0], vl[1]);
                MMA_BF16(o[2 * j + 1], ph, vl[2], vl[3]);
                MMA_BF16(o[2 * j],     pl, vh[0], vh[1]);
                MMA_BF16(o[2 * j + 1], pl, vh[2], vh[3]);
            }
        }

        __syncthreads();        // all warps done reading V(kt)
        if (more) {             // V(kt+1) loads during next S phase
#pragma unroll
            for (int i = 0; i < 8; i++) {
                const char* g = (i < 4) ? Vh : Vl;
                const int row = ((i & 3) << 4) + rI;
                cpa16(sb + FVHI + (uint32_t)(i >> 2) * FT
                         + (uint32_t)row * QROW_B + c16,
                      g + (rn + row) * 2048 + hoff + c16);
            }
            CP_COMMIT;
        }
    }

    // ---- epilogue: write hi/lo bf16 ----
    const int g  = lane >> 2;
    const int c2 = (lane & 3) * 2;
    const float inv0 = 1.f / l_s[0];
    const float inv1 = 1.f / l_s[1];
    const size_t row0 = rq + (size_t)(wid * 16 + g);
#pragma unroll
    for (int j = 0; j < 8; j++) {
        float a0 = o[j][0] * inv0, a1 = o[j][1] * inv0;
        float a2 = o[j][2] * inv1, a3 = o[j][3] * inv1;
        size_t i0 = (row0 * DM + h * DH + j * 8 + c2) >> 1;
        size_t i1 = ((row0 + 8) * DM + h * DH + j * 8 + c2) >> 1;
        Oh[i0] = pack_hi2(a0, a1);
        Ol[i0] = pack_rn2(a0 - trunc_hi(a0), a1 - trunc_hi(a1));
        Oh[i1] = pack_hi2(a2, a3);
        Ol[i1] = pack_rn2(a2 - trunc_hi(a2), a3 - trunc_hi(a3));
    }
}

// ---------------------------------------------------------------------------
// Launch
// ---------------------------------------------------------------------------
extern "C" void kernel_launch(void* const* d_in, const int* in_sizes, int n_in,
                              void* d_out, int out_size) {
    const float* x   = (const float*)d_in[0];
    const float* src = (const float*)d_in[1];
    const float* Wq  = (const float*)d_in[2];
    const float* Wk  = (const float*)d_in[3];
    const float* Wv  = (const float*)d_in[4];
    const float* Wo  = (const float*)d_in[5];
    float* out = (float*)d_out;

    void *xh, *xl, *sh, *sl, *qh, *ql, *kh, *kl, *vh, *vl, *oh, *ol;
    void *wqh, *wql, *wkh, *wkl, *wvh, *wvl, *woh, *wol;
    cudaGetSymbolAddress(&xh, g_xh);  cudaGetSymbolAddress(&xl, g_xl);
    cudaGetSymbolAddress(&sh, g_sh);  cudaGetSymbolAddress(&sl, g_sl);
    cudaGetSymbolAddress(&qh, g_qh);  cudaGetSymbolAddress(&ql, g_ql);
    cudaGetSymbolAddress(&kh, g_kh);  cudaGetSymbolAddress(&kl, g_kl);
    cudaGetSymbolAddress(&vh, g_vh);  cudaGetSymbolAddress(&vl, g_vl);
    cudaGetSymbolAddress(&oh, g_oh);  cudaGetSymbolAddress(&ol, g_ol);
    cudaGetSymbolAddress(&wqh, g_wqh); cudaGetSymbolAddress(&wql, g_wql);
    cudaGetSymbolAddress(&wkh, g_wkh); cudaGetSymbolAddress(&wkl, g_wkl);
    cudaGetSymbolAddress(&wvh, g_wvh); cudaGetSymbolAddress(&wvl, g_wvl);
    cudaGetSymbolAddress(&woh, g_woh); cudaGetSymbolAddress(&wol, g_wol);

    cudaFuncSetAttribute(gemm_qkv2, cudaFuncAttributeMaxDynamicSharedMemorySize, GSMEM);
    cudaFuncSetAttribute(gemm_out2, cudaFuncAttributeMaxDynamicSharedMemorySize, GSMEM);
    cudaFuncSetAttribute(flash_v5, cudaFuncAttributeMaxDynamicSharedMemorySize, FSMEM);

    const float qs = 0.125f * 1.4426950408889634f;   // scale * log2(e)
    const int n4x = M_TOT * DM / 4;   // 1048576
    const int n4w = DM * DM / 4;      // 262144

    prep_split<<<n4x / 256, 256>>>((const float4*)x,   (uint2*)xh, (uint2*)xl, n4x, 1.f);
    prep_split<<<n4x / 256, 256>>>((const float4*)src, (uint2*)sh, (uint2*)sl, n4x, 1.f);
    prep_split<<<n4w / 256, 256>>>((const float4*)Wq,  (uint2*)wqh, (uint2*)wql, n4w, qs);
    prep_split<<<n4w / 256, 256>>>((const float4*)Wk,  (uint2*)wkh, (uint2*)wkl, n4w, 1.f);
    prep_split<<<n4w / 256, 256>>>((const float4*)Wv,  (uint2*)wvh, (uint2*)wvl, n4w, 1.f);
    prep_split<<<n4w / 256, 256>>>((const float4*)Wo,  (uint2*)woh, (uint2*)wol, n4w, 1.f);

    dim3 qkvgrid(DM / 128, M_TOT / 128, 3);   // (8, 32, 3)
    gemm_qkv2<<<qkvgrid, 256, GSMEM>>>(
        (const char*)xh, (const char*)xl, (const char*)sh, (const char*)sl,
        (const char*)wqh, (const char*)wql, (const char*)wkh, (const char*)wkl,
        (const char*)wvh, (const char*)wvl,
        (uint32_t*)qh, (uint32_t*)ql, (uint32_t*)kh, (uint32_t*)kl,
        (uint32_t*)vh, (uint32_t*)vl);

    dim3 agrid(SEQ / 64, NH, BATCH);          // (32, 16, 2)
    flash_v5<<<agrid, 128, FSMEM>>>(
        (const char*)qh, (const char*)ql, (const char*)kh, (const char*)kl,
        (const char*)vh, (const char*)vl, (uint32_t*)oh, (uint32_t*)ol);

    dim3 ggrid(DM / 128, M_TOT / 128);        // (8, 32)
    gemm_out2<<<ggrid, 256, GSMEM>>>(
        (const char*)oh, (const char*)ol, (const char*)woh, (const char*)wol, out);
}

// round 9
// speedup vs baseline: 1.1641x; 1.1641x over previous
#include <cuda_runtime.h>
#include <cuda_fp16.h>
#include <cstdint>

#define DM     1024
#define NH     16
#define DH     64
#define SEQ    2048
#define BATCH  2
#define M_TOT  (BATCH * SEQ)   // 4096

// ---- pre-split fp16 scratch ----
__device__ __half g_xh[(size_t)M_TOT * DM], g_xl[(size_t)M_TOT * DM];
__device__ __half g_sh[(size_t)M_TOT * DM], g_sl[(size_t)M_TOT * DM];
__device__ __half g_qh[(size_t)M_TOT * DM], g_ql[(size_t)M_TOT * DM];
__device__ __half g_kh[(size_t)M_TOT * DM], g_kl[(size_t)M_TOT * DM];
__device__ __half g_vh[(size_t)M_TOT * DM], g_vl[(size_t)M_TOT * DM];
__device__ __half g_o16[(size_t)M_TOT * DM];
__device__ __half g_wqh[DM * DM], g_wql[DM * DM];
__device__ __half g_wkh[DM * DM], g_wkl[DM * DM];
__device__ __half g_wvh[DM * DM], g_wvl[DM * DM];
__device__ __half g_woh[DM * DM], g_wol[DM * DM];

// ===========================================================================
// Helpers
// ===========================================================================
__device__ __forceinline__ uint32_t smem_u32(const void* p) {
    uint32_t a;
    asm("{ .reg .u64 t; cvta.to.shared.u64 t, %1; cvt.u32.u64 %0, t; }"
        : "=r"(a) : "l"(p));
    return a;
}
__device__ __forceinline__ void ldsm4(uint32_t* r, uint32_t addr) {
    asm volatile("ldmatrix.sync.aligned.m8n8.x4.shared.b16 {%0,%1,%2,%3}, [%4];"
                 : "=r"(r[0]), "=r"(r[1]), "=r"(r[2]), "=r"(r[3]) : "r"(addr));
}
__device__ __forceinline__ void ldsm4t(uint32_t* r, uint32_t addr) {
    asm volatile("ldmatrix.sync.aligned.m8n8.x4.trans.shared.b16 {%0,%1,%2,%3}, [%4];"
                 : "=r"(r[0]), "=r"(r[1]), "=r"(r[2]), "=r"(r[3]) : "r"(addr));
}
__device__ __forceinline__ void cpa16(uint32_t saddr, const void* gaddr) {
    asm volatile("cp.async.cg.shared.global [%0], [%1], 16;"
                 :: "r"(saddr), "l"(gaddr) : "memory");
}
#define CP_COMMIT asm volatile("cp.async.commit_group;" ::: "memory")
#define CP_WAIT0  asm volatile("cp.async.wait_group 0;" ::: "memory")
#define CP_WAIT1  asm volatile("cp.async.wait_group 1;" ::: "memory")

#define MMA_F16(d, a, b0, b1) \
    asm volatile("mma.sync.aligned.m16n8k16.row.col.f32.f16.f16.f32 " \
                 "{%0,%1,%2,%3},{%4,%5,%6,%7},{%8,%9},{%0,%1,%2,%3};" \
                 : "+f"((d)[0]), "+f"((d)[1]), "+f"((d)[2]), "+f"((d)[3]) \
                 : "r"((a)[0]), "r"((a)[1]), "r"((a)[2]), "r"((a)[3]), \
                   "r"(b0), "r"(b1))

__device__ __forceinline__ uint32_t pack_h2(float x, float y) {
    __half2 p = __floats2half2_rn(x, y);
    return *reinterpret_cast<uint32_t*>(&p);
}
// exact fp16 split of an fp32 pair -> (hi, lo) packed half2
__device__ __forceinline__ void split2f(float x, float y,
                                        uint32_t& h, uint32_t& l) {
    float hx = __half2float(__float2half_rn(x));
    float hy = __half2float(__float2half_rn(y));
    h = pack_h2(hx, hy);
    l = pack_h2(x - hx, y - hy);
}
__device__ __forceinline__ float fexp2(float x) {
    x = fmaxf(x, -126.0f);
    float z = x + 12582912.0f;
    float f = x - (z - 12582912.0f);
    float p = 0.0013333558f;
    p = fmaf(p, f, 0.0096181291f);
    p = fmaf(p, f, 0.0555041087f);
    p = fmaf(p, f, 0.2402265069f);
    p = fmaf(p, f, 0.6931471806f);
    p = fmaf(p, f, 1.0f);
    return __uint_as_float(__float_as_uint(p) + (__float_as_uint(z) << 23));
}

// ===========================================================================
// Prep: fp32 -> exact fp16 (hi, lo) split, optional scale.
// ===========================================================================
__global__ __launch_bounds__(256) void prep_split16(const float4* __restrict__ in,
                                                    uint2* __restrict__ hi,
                                                    uint2* __restrict__ lo,
                                                    int n4, float scale) {
    int i = blockIdx.x * blockDim.x + threadIdx.x;
    if (i >= n4) return;
    float4 v = in[i];
    v.x *= scale; v.y *= scale; v.z *= scale; v.w *= scale;
    uint32_t h0, l0, h1, l1;
    split2f(v.x, v.y, h0, l0);
    split2f(v.z, v.w, h1, l1);
    hi[i] = make_uint2(h0, h1);
    lo[i] = make_uint2(l0, l1);
}

// ===========================================================================
// fp16 split GEMM core: Y = A @ B^T.
// SPLITA=1: 3-MMA (Ah*Bh + Ah*Bl + Al*Bh)   [logit path]
// SPLITA=0: 2-MMA (Ah*Bh + Ah*Bl)           [value path]
// 128x128 CTA tile, KC=32, cp.async double-buffer.
// Stage layout: [Ah, Al, Bh, Bl] tiles of 128 rows x 80B.
// ===========================================================================
#define LDT2 80
#define TILE_BYTES (128 * LDT2)          // 10240
#define STAGE_BYTES (4 * TILE_BYTES)
#define GSMEM (2 * STAGE_BYTES)          // 81920

template<int SPLITA>
__device__ __forceinline__ void g_issue(uint32_t ss, const char* Ah,
                                        const char* Al, const char* Bh,
                                        const char* Bl, int m0, int n0,
                                        uint32_t k0b, int t) {
    const int row = ((t & 1) ? 64 : 0) + (t >> 2);   // unused helper removed
}

template<int SPLITA>
__device__ __forceinline__ void g_issue2(uint32_t ss, const char* Ah,
                                         const char* Al, const char* Bh,
                                         const char* Bl, int m0, int n0,
                                         uint32_t k0b, int t) {
    const int NOPS = SPLITA ? 8 : 6;
#pragma unroll
    for (int i = 0; i < NOPS; i++) {
        const char* g; uint32_t slot; int r0;
        if (SPLITA) {
            g    = (i < 2) ? Ah : (i < 4) ? Al : (i < 6) ? Bh : Bl;
            slot = (uint32_t)(i >> 1);
            r0   = (i < 4) ? m0 : n0;
        } else {
            g    = (i < 2) ? Ah : (i < 4) ? Bh : Bl;
            slot = (i < 2) ? 0u : (i < 4) ? 2u : 3u;
            r0   = (i < 2) ? m0 : n0;
        }
        const int row = ((i & 1) << 6) + (t >> 2);
        const uint32_t c16 = (uint32_t)(t & 3) << 4;
        cpa16(ss + slot * (uint32_t)TILE_BYTES + (uint32_t)row * LDT2 + c16,
              g + (size_t)(r0 + row) * 2048 + k0b + c16);
    }
}

template<int SPLITA>
__device__ __forceinline__ void gemm_core(const char* Ah, const char* Al,
                                          const char* Bh, const char* Bl,
                                          uint32_t sbase, int m0, int n0,
                                          float (&acc)[4][4][4]) {
    const int t    = threadIdx.x;
    const int lane = t & 31;
    const int wid  = t >> 5;
    const int wm   = wid & 1;
    const int wn   = wid >> 1;

#pragma unroll
    for (int mi = 0; mi < 4; mi++)
#pragma unroll
        for (int ni = 0; ni < 4; ni++)
#pragma unroll
            for (int e = 0; e < 4; e++) acc[mi][ni][e] = 0.f;

    const int r8  = lane & 7;
    const int sel = lane >> 3;
    const uint32_t aRowOff = (uint32_t)(wm * 64 + (sel & 1) * 8 + r8) * LDT2
                           + (uint32_t)((sel >> 1) * 8) * 2;
    const uint32_t bRowOff = (uint32_t)(wn * 32 + (sel >> 1) * 8 + r8) * LDT2
                           + (uint32_t)((sel & 1) * 8) * 2;

    auto compute = [&](uint32_t sb) {
        const uint32_t sA  = sb;
        const uint32_t sAl = sb + TILE_BYTES;
        const uint32_t sBh = sb + 2 * TILE_BYTES;
        const uint32_t sBl = sb + 3 * TILE_BYTES;
#pragma unroll
        for (int ks = 0; ks < 2; ks++) {
            const uint32_t kb = (uint32_t)ks * 32;
            uint32_t ah[4][4];
#pragma unroll
            for (int mi = 0; mi < 4; mi++)
                ldsm4(ah[mi], sA + aRowOff + (uint32_t)(mi * 16) * LDT2 + kb);
            uint32_t bh[2][4];
#pragma unroll
            for (int np = 0; np < 2; np++)
                ldsm4(bh[np], sBh + bRowOff + (uint32_t)(np * 16) * LDT2 + kb);
#pragma unroll
            for (int mi = 0; mi < 4; mi++)
#pragma unroll
                for (int ni = 0; ni < 4; ni++)
                    MMA_F16(acc[mi][ni], ah[mi],
                            bh[ni >> 1][(ni & 1) * 2],
                            bh[ni >> 1][(ni & 1) * 2 + 1]);
            uint32_t bl[2][4];
#pragma unroll
            for (int np = 0; np < 2; np++)
                ldsm4(bl[np], sBl + bRowOff + (uint32_t)(np * 16) * LDT2 + kb);
#pragma unroll
            for (int mi = 0; mi < 4; mi++)
#pragma unroll
                for (int ni = 0; ni < 4; ni++)
                    MMA_F16(acc[mi][ni], ah[mi],
                            bl[ni >> 1][(ni & 1) * 2],
                            bl[ni >> 1][(ni & 1) * 2 + 1]);
            if (SPLITA) {
                uint32_t al[4][4];
#pragma unroll
                for (int mi = 0; mi < 4; mi++)
                    ldsm4(al[mi], sAl + aRowOff + (uint32_t)(mi * 16) * LDT2 + kb);
#pragma unroll
                for (int mi = 0; mi < 4; mi++)
#pragma unroll
                    for (int ni = 0; ni < 4; ni++)
                        MMA_F16(acc[mi][ni], al[mi],
                                bh[ni >> 1][(ni & 1) * 2],
                                bh[ni >> 1][(ni & 1) * 2 + 1]);
            }
        }
    };

    g_issue2<SPLITA>(sbase, Ah, Al, Bh, Bl, m0, n0, 0u, t);
    CP_COMMIT;

    const int NCHUNK = DM / 32;   // 32
    for (int chunk = 0; chunk < NCHUNK; chunk++) {
        const int s = chunk & 1;
        CP_WAIT0;
        __syncthreads();
        if (chunk + 1 < NCHUNK) {
            g_issue2<SPLITA>(sbase + (uint32_t)(s ^ 1) * STAGE_BYTES,
                             Ah, Al, Bh, Bl, m0, n0,
                             (uint32_t)(chunk + 1) * 64, t);
            CP_COMMIT;
        }
        compute(sbase + (uint32_t)s * STAGE_BYTES);
    }
}

// QKV projections: z=0: Q=x@Wq^T (3-MMA), z=1: K=src@Wk^T (3-MMA),
// z=2: V=src@Wv^T (2-MMA). All epilogues write exact fp16 hi/lo.
__global__ __launch_bounds__(256, 2)
void gemm_qkv3(const char* xh, const char* xl, const char* sh, const char* sl,
               const char* wqh, const char* wql, const char* wkh, const char* wkl,
               const char* wvh, const char* wvl,
               uint32_t* qh, uint32_t* ql, uint32_t* kh, uint32_t* kl,
               uint32_t* vh, uint32_t* vl) {
    extern __shared__ __align__(16) char sm[];
    const int z  = blockIdx.z;
    const int m0 = blockIdx.y * 128;
    const int n0 = blockIdx.x * 128;

    float acc[4][4][4];
    if (z == 0)      gemm_core<1>(xh, xl, wqh, wql, smem_u32(sm), m0, n0, acc);
    else if (z == 1) gemm_core<1>(sh, sl, wkh, wkl, smem_u32(sm), m0, n0, acc);
    else             gemm_core<0>(sh, sh, wvh, wvl, smem_u32(sm), m0, n0, acc);

    uint32_t* Yh = (z == 0) ? qh : (z == 1 ? kh : vh);
    uint32_t* Yl = (z == 0) ? ql : (z == 1 ? kl : vl);

    const int lane = threadIdx.x & 31;
    const int wid  = threadIdx.x >> 5;
    const int wm   = wid & 1, wn = wid >> 1;
    const int g  = lane >> 2;
    const int c2 = (lane & 3) * 2;
#pragma unroll
    for (int mi = 0; mi < 4; mi++) {
#pragma unroll
        for (int ni = 0; ni < 4; ni++) {
            int row = m0 + wm * 64 + mi * 16 + g;
            int col = n0 + wn * 32 + ni * 8 + c2;
            size_t i0 = ((size_t)row * DM + col) >> 1;
            size_t i1 = ((size_t)(row + 8) * DM + col) >> 1;
            uint32_t h, l;
            split2f(acc[mi][ni][0], acc[mi][ni][1], h, l);
            Yh[i0] = h; Yl[i0] = l;
            split2f(acc[mi][ni][2], acc[mi][ni][3], h, l);
            Yh[i1] = h; Yl[i1] = l;
        }
    }
}

// Output projection: O(plain fp16) @ Wo^T (2-MMA), fp32 epilogue.
__global__ __launch_bounds__(256, 2)
void gemm_out3(const char* o16, const char* wh, const char* wl,
               float* __restrict__ Y) {
    extern __shared__ __align__(16) char sm[];
    const int m0 = blockIdx.y * 128;
    const int n0 = blockIdx.x * 128;

    float acc[4][4][4];
    gemm_core<0>(o16, o16, wh, wl, smem_u32(sm), m0, n0, acc);

    const int lane = threadIdx.x & 31;
    const int wid  = threadIdx.x >> 5;
    const int wm   = wid & 1, wn = wid >> 1;
    const int g  = lane >> 2;
    const int c2 = (lane & 3) * 2;
#pragma unroll
    for (int mi = 0; mi < 4; mi++) {
#pragma unroll
        for (int ni = 0; ni < 4; ni++) {
            int row = m0 + wm * 64 + mi * 16 + g;
            int col = n0 + wn * 32 + ni * 8 + c2;
            float2 v0 = {acc[mi][ni][0], acc[mi][ni][1]};
            float2 v1 = {acc[mi][ni][2], acc[mi][ni][3]};
            *(float2*)(Y + (size_t)row * DM + col)       = v0;
            *(float2*)(Y + (size_t)(row + 8) * DM + col) = v1;
        }
    }
}

// ===========================================================================
// Flash attention v6 (fp16): QK 3-MMA split; PV 2-MMA (P plain, V split).
// 128 threads / 64 q-rows, 4 CTAs/SM, cp.async K/V overlap.
// ===========================================================================
#define QROW_B 144
#define FT     9216
#define FQHI   0
#define FQLO   (1 * FT)
#define FKHI   (2 * FT)
#define FKLO   (3 * FT)
#define FVHI   (4 * FT)
#define FVLO   (5 * FT)
#define FSMEM  (6 * FT)                  // 55296

__global__ __launch_bounds__(128, 4)
void flash_v6(const char* Qh, const char* Ql, const char* Kh, const char* Kl,
              const char* Vh, const char* Vl, uint32_t* O16) {
    extern __shared__ __align__(16) char fsm[];
    const uint32_t sb = smem_u32(fsm);

    const int t    = threadIdx.x;
    const int lane = t & 31;
    const int wid  = t >> 5;
    const int b    = blockIdx.z;
    const int h    = blockIdx.y;
    const int q0   = blockIdx.x * 64;
    const size_t rq  = (size_t)(b * SEQ + q0);
    const size_t rb0 = (size_t)(b * SEQ);
    const uint32_t hoff = (uint32_t)h * 128u;

    const int rI  = t >> 3;
    const uint32_t c16 = (uint32_t)(t & 7) << 4;

    // ---- Q group + K(0) group ----
#pragma unroll
    for (int i = 0; i < 8; i++) {
        const char* g = (i < 4) ? Qh : Ql;
        const int row = ((i & 3) << 4) + rI;
        cpa16(sb + (uint32_t)(i >> 2) * FT + (uint32_t)row * QROW_B + c16,
              g + (rq + row) * 2048 + hoff + c16);
    }
#pragma unroll
    for (int i = 0; i < 8; i++) {
        const char* g = (i < 4) ? Kh : Kl;
        const int row = ((i & 3) << 4) + rI;
        cpa16(sb + FKHI + (uint32_t)(i >> 2) * FT + (uint32_t)row * QROW_B + c16,
              g + (rb0 + row) * 2048 + hoff + c16);
    }
    CP_COMMIT;
#pragma unroll
    for (int i = 0; i < 8; i++) {
        const char* g = (i < 4) ? Vh : Vl;
        const int row = ((i & 3) << 4) + rI;
        cpa16(sb + FVHI + (uint32_t)(i >> 2) * FT + (uint32_t)row * QROW_B + c16,
              g + (rb0 + row) * 2048 + hoff + c16);
    }
    CP_COMMIT;

    const int r8  = lane & 7;
    const int sel = lane >> 3;
    const uint32_t aOff = (uint32_t)(wid * 16 + (sel & 1) * 8 + r8) * QROW_B
                        + (uint32_t)((sel >> 1) * 16);
    const uint32_t bOff = (uint32_t)((sel >> 1) * 8 + r8) * QROW_B
                        + (uint32_t)((sel & 1) * 16);
    const uint32_t vOff = (uint32_t)((sel & 1) * 8 + r8) * QROW_B
                        + (uint32_t)((sel >> 1) * 16);

    float m_s[2] = {-1.0e30f, -1.0e30f};
    float l_s[2] = {0.f, 0.f};
    float o[8][4];
#pragma unroll
    for (int j = 0; j < 8; j++)
#pragma unroll
        for (int e = 0; e < 4; e++) o[j][e] = 0.f;

    const int NT = SEQ / 64;
    for (int kt = 0; kt < NT; kt++) {
        const size_t rn = rb0 + (size_t)(kt + 1) * 64;
        const bool more = (kt + 1 < NT);

        CP_WAIT1;
        __syncthreads();

        // ---- S = Q @ K^T (3-MMA split) ----
        float s[8][4];
#pragma unroll
        for (int j = 0; j < 8; j++)
#pragma unroll
            for (int e = 0; e < 4; e++) s[j][e] = 0.f;

#pragma unroll
        for (int kc = 0; kc < 4; kc++) {
            const uint32_t kb = (uint32_t)kc * 32;
            uint32_t ahi[4], alo[4];
            ldsm4(ahi, sb + FQHI + aOff + kb);
            ldsm4(alo, sb + FQLO + aOff + kb);
#pragma unroll
            for (int j = 0; j < 4; j++) {
                const uint32_t rowj = (uint32_t)(j * 16) * QROW_B;
                uint32_t bh[4], bl[4];
                ldsm4(bh, sb + FKHI + bOff + rowj + kb);
                ldsm4(bl, sb + FKLO + bOff + rowj + kb);
                MMA_F16(s[2 * j],     ahi, bh[0], bh[1]);
                MMA_F16(s[2 * j + 1], ahi, bh[2], bh[3]);
                MMA_F16(s[2 * j],     ahi, bl[0], bl[1]);
                MMA_F16(s[2 * j + 1], ahi, bl[2], bl[3]);
                MMA_F16(s[2 * j],     alo, bh[0], bh[1]);
                MMA_F16(s[2 * j + 1], alo, bh[2], bh[3]);
            }
        }

        __syncthreads();
        if (more) {
#pragma unroll
            for (int i = 0; i < 8; i++) {
                const char* g = (i < 4) ? Kh : Kl;
                const int row = ((i & 3) << 4) + rI;
                cpa16(sb + FKHI + (uint32_t)(i >> 2) * FT
                         + (uint32_t)row * QROW_B + c16,
                      g + (rn + row) * 2048 + hoff + c16);
            }
            CP_COMMIT;
        }

        // ---- online softmax (log2 domain) ----
        float mx0 = s[0][0], mx1 = s[0][2];
#pragma unroll
        for (int j = 0; j < 8; j++) {
            mx0 = fmaxf(mx0, fmaxf(s[j][0], s[j][1]));
            mx1 = fmaxf(mx1, fmaxf(s[j][2], s[j][3]));
        }
        mx0 = fmaxf(mx0, __shfl_xor_sync(0xffffffffu, mx0, 1));
        mx0 = fmaxf(mx0, __shfl_xor_sync(0xffffffffu, mx0, 2));
        mx1 = fmaxf(mx1, __shfl_xor_sync(0xffffffffu, mx1, 1));
        mx1 = fmaxf(mx1, __shfl_xor_sync(0xffffffffu, mx1, 2));

        const float mn0 = fmaxf(m_s[0], mx0);
        const float mn1 = fmaxf(m_s[1], mx1);
        const float al0 = fexp2(m_s[0] - mn0);
        const float al1 = fexp2(m_s[1] - mn1);
        m_s[0] = mn0; m_s[1] = mn1;

        float sum0 = 0.f, sum1 = 0.f;
#pragma unroll
        for (int j = 0; j < 8; j++) {
            s[j][0] = fexp2(s[j][0] - mn0);
            s[j][1] = fexp2(s[j][1] - mn0);
            s[j][2] = fexp2(s[j][2] - mn1);
            s[j][3] = fexp2(s[j][3] - mn1);
            sum0 += s[j][0] + s[j][1];
            sum1 += s[j][2] + s[j][3];
        }
        sum0 += __shfl_xor_sync(0xffffffffu, sum0, 1);
        sum0 += __shfl_xor_sync(0xffffffffu, sum0, 2);
        sum1 += __shfl_xor_sync(0xffffffffu, sum1, 1);
        sum1 += __shfl_xor_sync(0xffffffffu, sum1, 2);
        l_s[0] = l_s[0] * al0 + sum0;
        l_s[1] = l_s[1] * al1 + sum1;

#pragma unroll
        for (int j = 0; j < 8; j++) {
            o[j][0] *= al0; o[j][1] *= al0;
            o[j][2] *= al1; o[j][3] *= al1;
        }

        if (more) { CP_WAIT1; } else { CP_WAIT0; }
        __syncthreads();

        // ---- PV: P plain fp16, V split (2-MMA) ----
#pragma unroll
        for (int kk = 0; kk < 4; kk++) {
            float* s0 = s[2 * kk];
            float* s1 = s[2 * kk + 1];
            uint32_t pa[4];
            pa[0] = pack_h2(s0[0], s0[1]);
            pa[1] = pack_h2(s0[2], s0[3]);
            pa[2] = pack_h2(s1[0], s1[1]);
            pa[3] = pack_h2(s1[2], s1[3]);
            const uint32_t rowk = (uint32_t)(kk * 16) * QROW_B;
#pragma unroll
            for (int j = 0; j < 4; j++) {
                uint32_t vh[4], vl[4];
                ldsm4t(vh, sb + FVHI + vOff + rowk + (uint32_t)(j * 32));
                ldsm4t(vl, sb + FVLO + vOff + rowk + (uint32_t)(j * 32));
                MMA_F16(o[2 * j],     pa, vh[0], vh[1]);
                MMA_F16(o[2 * j + 1], pa, vh[2], vh[3]);
                MMA_F16(o[2 * j],     pa, vl[0], vl[1]);
                MMA_F16(o[2 * j + 1], pa, vl[2], vl[3]);
            }
        }

        __syncthreads();
        if (more) {
#pragma unroll
            for (int i = 0; i < 8; i++) {
                const char* g = (i < 4) ? Vh : Vl;
                const int row = ((i & 3) << 4) + rI;
                cpa16(sb + FVHI + (uint32_t)(i >> 2) * FT
                         + (uint32_t)row * QROW_B + c16,
                      g + (rn + row) * 2048 + hoff + c16);
            }
            CP_COMMIT;
        }
    }

    // ---- epilogue: O plain fp16 ----
    const int g  = lane >> 2;
    const int c2 = (lane & 3) * 2;
    const float inv0 = 1.f / l_s[0];
    const float inv1 = 1.f / l_s[1];
    const size_t row0 = rq + (size_t)(wid * 16 + g);
#pragma unroll
    for (int j = 0; j < 8; j++) {
        size_t i0 = (row0 * DM + h * DH + j * 8 + c2) >> 1;
        size_t i1 = ((row0 + 8) * DM + h * DH + j * 8 + c2) >> 1;
        O16[i0] = pack_h2(o[j][0] * inv0, o[j][1] * inv0);
        O16[i1] = pack_h2(o[j][2] * inv1, o[j][3] * inv1);
    }
}

// ---------------------------------------------------------------------------
// Launch
// ---------------------------------------------------------------------------
extern "C" void kernel_launch(void* const* d_in, const int* in_sizes, int n_in,
                              void* d_out, int out_size) {
    const float* x   = (const float*)d_in[0];
    const float* src = (const float*)d_in[1];
    const float* Wq  = (const float*)d_in[2];
    const float* Wk  = (const float*)d_in[3];
    const float* Wv  = (const float*)d_in[4];
    const float* Wo  = (const float*)d_in[5];
    float* out = (float*)d_out;

    void *xh, *xl, *sh, *sl, *qh, *ql, *kh, *kl, *vh, *vl, *o16;
    void *wqh, *wql, *wkh, *wkl, *wvh, *wvl, *woh, *wol;
    cudaGetSymbolAddress(&xh, g_xh);  cudaGetSymbolAddress(&xl, g_xl);
    cudaGetSymbolAddress(&sh, g_sh);  cudaGetSymbolAddress(&sl, g_sl);
    cudaGetSymbolAddress(&qh, g_qh);  cudaGetSymbolAddress(&ql, g_ql);
    cudaGetSymbolAddress(&kh, g_kh);  cudaGetSymbolAddress(&kl, g_kl);
    cudaGetSymbolAddress(&vh, g_vh);  cudaGetSymbolAddress(&vl, g_vl);
    cudaGetSymbolAddress(&o16, g_o16);
    cudaGetSymbolAddress(&wqh, g_wqh); cudaGetSymbolAddress(&wql, g_wql);
    cudaGetSymbolAddress(&wkh, g_wkh); cudaGetSymbolAddress(&wkl, g_wkl);
    cudaGetSymbolAddress(&wvh, g_wvh); cudaGetSymbolAddress(&wvl, g_wvl);
    cudaGetSymbolAddress(&woh, g_woh); cudaGetSymbolAddress(&wol, g_wol);

    cudaFuncSetAttribute(gemm_qkv3, cudaFuncAttributeMaxDynamicSharedMemorySize, GSMEM);
    cudaFuncSetAttribute(gemm_out3, cudaFuncAttributeMaxDynamicSharedMemorySize, GSMEM);
    cudaFuncSetAttribute(flash_v6, cudaFuncAttributeMaxDynamicSharedMemorySize, FSMEM);

    const float qs = 0.125f * 1.4426950408889634f;
    const int n4x = M_TOT * DM / 4;
    const int n4w = DM * DM / 4;

    prep_split16<<<n4x / 256, 256>>>((const float4*)x,   (uint2*)xh, (uint2*)xl, n4x, 1.f);
    prep_split16<<<n4x / 256, 256>>>((const float4*)src, (uint2*)sh, (uint2*)sl, n4x, 1.f);
    prep_split16<<<n4w / 256, 256>>>((const float4*)Wq,  (uint2*)wqh, (uint2*)wql, n4w, qs);
    prep_split16<<<n4w / 256, 256>>>((const float4*)Wk,  (uint2*)wkh, (uint2*)wkl, n4w, 1.f);
    prep_split16<<<n4w / 256, 256>>>((const float4*)Wv,  (uint2*)wvh, (uint2*)wvl, n4w, 1.f);
    prep_split16<<<n4w / 256, 256>>>((const float4*)Wo,  (uint2*)woh, (uint2*)wol, n4w, 1.f);

    dim3 qkvgrid(DM / 128, M_TOT / 128, 3);
    gemm_qkv3<<<qkvgrid, 256, GSMEM>>>(
        (const char*)xh, (const char*)xl, (const char*)sh, (const char*)sl,
        (const char*)wqh, (const char*)wql, (const char*)wkh, (const char*)wkl,
        (const char*)wvh, (const char*)wvl,
        (uint32_t*)qh, (uint32_t*)ql, (uint32_t*)kh, (uint32_t*)kl,
        (uint32_t*)vh, (uint32_t*)vl);

    dim3 agrid(SEQ / 64, NH, BATCH);
    flash_v6<<<agrid, 128, FSMEM>>>(
        (const char*)qh, (const char*)ql, (const char*)kh, (const char*)kl,
        (const char*)vh, (const char*)vl, (uint32_t*)o16);

    dim3 ggrid(DM / 128, M_TOT / 128);
    gemm_out3<<<ggrid, 256, GSMEM>>>(
        (const char*)o16, (const char*)woh, (const char*)wol, out);
}

// round 10
// speedup vs baseline: 1.4503x; 1.2458x over previous
#include <cuda_runtime.h>
#include <cuda_fp16.h>
#include <cstdint>

#define DM     1024
#define NH     16
#define DH     64
#define SEQ    2048
#define BATCH  2
#define M_TOT  (BATCH * SEQ)   // 4096

// ---- fp16 scratch ----
__device__ __half g_x16[(size_t)M_TOT * DM];          // x plain
__device__ __half g_s16[(size_t)M_TOT * DM];          // src plain
__device__ __half g_q16[(size_t)M_TOT * DM];          // Q plain (pre-scaled)
__device__ __half g_k16[(size_t)M_TOT * DM];          // K plain
__device__ __half g_vh[(size_t)M_TOT * DM], g_vl[(size_t)M_TOT * DM];
__device__ __half g_o16[(size_t)M_TOT * DM];          // attn out plain
__device__ __half g_wqh[DM * DM], g_wql[DM * DM];
__device__ __half g_wkh[DM * DM], g_wkl[DM * DM];
__device__ __half g_wvh[DM * DM], g_wvl[DM * DM];
__device__ __half g_woh[DM * DM], g_wol[DM * DM];

// ===========================================================================
// Helpers
// ===========================================================================
__device__ __forceinline__ uint32_t smem_u32(const void* p) {
    uint32_t a;
    asm("{ .reg .u64 t; cvta.to.shared.u64 t, %1; cvt.u32.u64 %0, t; }"
        : "=r"(a) : "l"(p));
    return a;
}
__device__ __forceinline__ void ldsm4(uint32_t* r, uint32_t addr) {
    asm volatile("ldmatrix.sync.aligned.m8n8.x4.shared.b16 {%0,%1,%2,%3}, [%4];"
                 : "=r"(r[0]), "=r"(r[1]), "=r"(r[2]), "=r"(r[3]) : "r"(addr));
}
__device__ __forceinline__ void ldsm4t(uint32_t* r, uint32_t addr) {
    asm volatile("ldmatrix.sync.aligned.m8n8.x4.trans.shared.b16 {%0,%1,%2,%3}, [%4];"
                 : "=r"(r[0]), "=r"(r[1]), "=r"(r[2]), "=r"(r[3]) : "r"(addr));
}
__device__ __forceinline__ void cpa16(uint32_t saddr, const void* gaddr) {
    asm volatile("cp.async.cg.shared.global [%0], [%1], 16;"
                 :: "r"(saddr), "l"(gaddr) : "memory");
}
#define CP_COMMIT asm volatile("cp.async.commit_group;" ::: "memory")
#define CP_WAIT0  asm volatile("cp.async.wait_group 0;" ::: "memory")
#define CP_WAIT1  asm volatile("cp.async.wait_group 1;" ::: "memory")

#define MMA_F16(d, a, b0, b1) \
    asm volatile("mma.sync.aligned.m16n8k16.row.col.f32.f16.f16.f32 " \
                 "{%0,%1,%2,%3},{%4,%5,%6,%7},{%8,%9},{%0,%1,%2,%3};" \
                 : "+f"((d)[0]), "+f"((d)[1]), "+f"((d)[2]), "+f"((d)[3]) \
                 : "r"((a)[0]), "r"((a)[1]), "r"((a)[2]), "r"((a)[3]), \
                   "r"(b0), "r"(b1))

__device__ __forceinline__ uint32_t pack_h2(float x, float y) {
    __half2 p = __floats2half2_rn(x, y);
    return *reinterpret_cast<uint32_t*>(&p);
}
__device__ __forceinline__ void split2f(float x, float y,
                                        uint32_t& h, uint32_t& l) {
    float hx = __half2float(__float2half_rn(x));
    float hy = __half2float(__float2half_rn(y));
    h = pack_h2(hx, hy);
    l = pack_h2(x - hx, y - hy);
}
__device__ __forceinline__ float fexp2(float x) {
    x = fmaxf(x, -126.0f);
    float z = x + 12582912.0f;
    float f = x - (z - 12582912.0f);
    float p = 0.0013333558f;
    p = fmaf(p, f, 0.0096181291f);
    p = fmaf(p, f, 0.0555041087f);
    p = fmaf(p, f, 0.2402265069f);
    p = fmaf(p, f, 0.6931471806f);
    p = fmaf(p, f, 1.0f);
    return __uint_as_float(__float_as_uint(p) + (__float_as_uint(z) << 23));
}

// ===========================================================================
// Prep kernels
// ===========================================================================
__global__ __launch_bounds__(256) void prep_split16(const float4* __restrict__ in,
                                                    uint2* __restrict__ hi,
                                                    uint2* __restrict__ lo,
                                                    int n4, float scale) {
    int i = blockIdx.x * blockDim.x + threadIdx.x;
    if (i >= n4) return;
    float4 v = in[i];
    v.x *= scale; v.y *= scale; v.z *= scale; v.w *= scale;
    uint32_t h0, l0, h1, l1;
    split2f(v.x, v.y, h0, l0);
    split2f(v.z, v.w, h1, l1);
    hi[i] = make_uint2(h0, h1);
    lo[i] = make_uint2(l0, l1);
}
__global__ __launch_bounds__(256) void prep_rn16(const float4* __restrict__ in,
                                                 uint2* __restrict__ out, int n4) {
    int i = blockIdx.x * blockDim.x + threadIdx.x;
    if (i >= n4) return;
    float4 v = in[i];
    out[i] = make_uint2(pack_h2(v.x, v.y), pack_h2(v.z, v.w));
}

// ===========================================================================
// fp16 GEMM core (2-MMA value-path form): Y = A_rn @ (B_hi + B_lo)^T.
// 128x128 CTA tile, KC=32, cp.async double-buffer.
// Stage layout: [A, -, Bh, Bl] tiles of 128 rows x 80B.
// ===========================================================================
#define LDT2 80
#define TILE_BYTES (128 * LDT2)          // 10240
#define STAGE_BYTES (4 * TILE_BYTES)
#define GSMEM (2 * STAGE_BYTES)          // 81920

__device__ __forceinline__ void g_issue2(uint32_t ss, const char* A,
                                         const char* Bh, const char* Bl,
                                         int m0, int n0, uint32_t k0b, int t) {
#pragma unroll
    for (int i = 0; i < 6; i++) {
        const char* g = (i < 2) ? A : (i < 4) ? Bh : Bl;
        const uint32_t slot = (i < 2) ? 0u : (i < 4) ? 2u : 3u;
        const int r0 = (i < 2) ? m0 : n0;
        const int row = ((i & 1) << 6) + (t >> 2);
        const uint32_t c16 = (uint32_t)(t & 3) << 4;
        cpa16(ss + slot * (uint32_t)TILE_BYTES + (uint32_t)row * LDT2 + c16,
              g + (size_t)(r0 + row) * 2048 + k0b + c16);
    }
}

__device__ __forceinline__ void gemm_core2(const char* A, const char* Bh,
                                           const char* Bl, uint32_t sbase,
                                           int m0, int n0,
                                           float (&acc)[4][4][4]) {
    const int t    = threadIdx.x;
    const int lane = t & 31;
    const int wid  = t >> 5;
    const int wm   = wid & 1;
    const int wn   = wid >> 1;

#pragma unroll
    for (int mi = 0; mi < 4; mi++)
#pragma unroll
        for (int ni = 0; ni < 4; ni++)
#pragma unroll
            for (int e = 0; e < 4; e++) acc[mi][ni][e] = 0.f;

    const int r8  = lane & 7;
    const int sel = lane >> 3;
    const uint32_t aRowOff = (uint32_t)(wm * 64 + (sel & 1) * 8 + r8) * LDT2
                           + (uint32_t)((sel >> 1) * 8) * 2;
    const uint32_t bRowOff = (uint32_t)(wn * 32 + (sel >> 1) * 8 + r8) * LDT2
                           + (uint32_t)((sel & 1) * 8) * 2;

    auto compute = [&](uint32_t sb) {
        const uint32_t sA  = sb;
        const uint32_t sBh = sb + 2 * TILE_BYTES;
        const uint32_t sBl = sb + 3 * TILE_BYTES;
#pragma unroll
        for (int ks = 0; ks < 2; ks++) {
            const uint32_t kb = (uint32_t)ks * 32;
            uint32_t ah[4][4];
#pragma unroll
            for (int mi = 0; mi < 4; mi++)
                ldsm4(ah[mi], sA + aRowOff + (uint32_t)(mi * 16) * LDT2 + kb);
            uint32_t bh[2][4];
#pragma unroll
            for (int np = 0; np < 2; np++)
                ldsm4(bh[np], sBh + bRowOff + (uint32_t)(np * 16) * LDT2 + kb);
#pragma unroll
            for (int mi = 0; mi < 4; mi++)
#pragma unroll
                for (int ni = 0; ni < 4; ni++)
                    MMA_F16(acc[mi][ni], ah[mi],
                            bh[ni >> 1][(ni & 1) * 2],
                            bh[ni >> 1][(ni & 1) * 2 + 1]);
            uint32_t bl[2][4];
#pragma unroll
            for (int np = 0; np < 2; np++)
                ldsm4(bl[np], sBl + bRowOff + (uint32_t)(np * 16) * LDT2 + kb);
#pragma unroll
            for (int mi = 0; mi < 4; mi++)
#pragma unroll
                for (int ni = 0; ni < 4; ni++)
                    MMA_F16(acc[mi][ni], ah[mi],
                            bl[ni >> 1][(ni & 1) * 2],
                            bl[ni >> 1][(ni & 1) * 2 + 1]);
        }
    };

    g_issue2(sbase, A, Bh, Bl, m0, n0, 0u, t);
    CP_COMMIT;

    const int NCHUNK = DM / 32;
    for (int chunk = 0; chunk < NCHUNK; chunk++) {
        const int s = chunk & 1;
        CP_WAIT0;
        __syncthreads();
        if (chunk + 1 < NCHUNK) {
            g_issue2(sbase + (uint32_t)(s ^ 1) * STAGE_BYTES,
                     A, Bh, Bl, m0, n0, (uint32_t)(chunk + 1) * 64, t);
            CP_COMMIT;
        }
        compute(sbase + (uint32_t)s * STAGE_BYTES);
    }
}

// QKV projections: z=0: Q (plain fp16 out), z=1: K (plain), z=2: V (split out).
__global__ __launch_bounds__(256, 2)
void gemm_qkv4(const char* x16, const char* s16,
               const char* wqh, const char* wql, const char* wkh, const char* wkl,
               const char* wvh, const char* wvl,
               uint32_t* q16, uint32_t* k16, uint32_t* vh, uint32_t* vl) {
    extern __shared__ __align__(16) char sm[];
    const int z  = blockIdx.z;
    const int m0 = blockIdx.y * 128;
    const int n0 = blockIdx.x * 128;

    float acc[4][4][4];
    if (z == 0)      gemm_core2(x16, wqh, wql, smem_u32(sm), m0, n0, acc);
    else if (z == 1) gemm_core2(s16, wkh, wkl, smem_u32(sm), m0, n0, acc);
    else             gemm_core2(s16, wvh, wvl, smem_u32(sm), m0, n0, acc);

    const int lane = threadIdx.x & 31;
    const int wid  = threadIdx.x >> 5;
    const int wm   = wid & 1, wn = wid >> 1;
    const int g  = lane >> 2;
    const int c2 = (lane & 3) * 2;
#pragma unroll
    for (int mi = 0; mi < 4; mi++) {
#pragma unroll
        for (int ni = 0; ni < 4; ni++) {
            int row = m0 + wm * 64 + mi * 16 + g;
            int col = n0 + wn * 32 + ni * 8 + c2;
            size_t i0 = ((size_t)row * DM + col) >> 1;
            size_t i1 = ((size_t)(row + 8) * DM + col) >> 1;
            if (z < 2) {
                uint32_t* Y = (z == 0) ? q16 : k16;
                Y[i0] = pack_h2(acc[mi][ni][0], acc[mi][ni][1]);
                Y[i1] = pack_h2(acc[mi][ni][2], acc[mi][ni][3]);
            } else {
                uint32_t h, l;
                split2f(acc[mi][ni][0], acc[mi][ni][1], h, l);
                vh[i0] = h; vl[i0] = l;
                split2f(acc[mi][ni][2], acc[mi][ni][3], h, l);
                vh[i1] = h; vl[i1] = l;
            }
        }
    }
}

// Output projection: O(plain fp16) @ Wo^T (2-MMA), fp32 epilogue.
__global__ __launch_bounds__(256, 2)
void gemm_out4(const char* o16, const char* wh, const char* wl,
               float* __restrict__ Y) {
    extern __shared__ __align__(16) char sm[];
    const int m0 = blockIdx.y * 128;
    const int n0 = blockIdx.x * 128;

    float acc[4][4][4];
    gemm_core2(o16, wh, wl, smem_u32(sm), m0, n0, acc);

    const int lane = threadIdx.x & 31;
    const int wid  = threadIdx.x >> 5;
    const int wm   = wid & 1, wn = wid >> 1;
    const int g  = lane >> 2;
    const int c2 = (lane & 3) * 2;
#pragma unroll
    for (int mi = 0; mi < 4; mi++) {
#pragma unroll
        for (int ni = 0; ni < 4; ni++) {
            int row = m0 + wm * 64 + mi * 16 + g;
            int col = n0 + wn * 32 + ni * 8 + c2;
            float2 v0 = {acc[mi][ni][0], acc[mi][ni][1]};
            float2 v1 = {acc[mi][ni][2], acc[mi][ni][3]};
            *(float2*)(Y + (size_t)row * DM + col)       = v0;
            *(float2*)(Y + (size_t)(row + 8) * DM + col) = v1;
        }
    }
}

// ===========================================================================
// Flash attention v7 (fp16): QK 1-MMA (Q, K plain); PV 2-MMA (P plain, V split).
// 128 threads / 64 q-rows, 4 CTAs/SM, cp.async K/V overlap.
// ===========================================================================
#define QROW_B 144
#define FT     9216
#define FQ     0
#define FK     (1 * FT)
#define FVHI   (2 * FT)
#define FVLO   (3 * FT)
#define FSMEM  (4 * FT)                  // 36864

__global__ __launch_bounds__(128, 4)
void flash_v7(const char* Q16, const char* K16,
              const char* Vh, const char* Vl, uint32_t* O16) {
    extern __shared__ __align__(16) char fsm[];
    const uint32_t sb = smem_u32(fsm);

    const int t    = threadIdx.x;
    const int lane = t & 31;
    const int wid  = t >> 5;
    const int b    = blockIdx.z;
    const int h    = blockIdx.y;
    const int q0   = blockIdx.x * 64;
    const size_t rq  = (size_t)(b * SEQ + q0);
    const size_t rb0 = (size_t)(b * SEQ);
    const uint32_t hoff = (uint32_t)h * 128u;

    const int rI  = t >> 3;
    const uint32_t c16 = (uint32_t)(t & 7) << 4;

    // ---- group 1: Q + K(0) ----
#pragma unroll
    for (int i = 0; i < 4; i++) {
        const int row = (i << 4) + rI;
        cpa16(sb + FQ + (uint32_t)row * QROW_B + c16,
              Q16 + (rq + row) * 2048 + hoff + c16);
    }
#pragma unroll
    for (int i = 0; i < 4; i++) {
        const int row = (i << 4) + rI;
        cpa16(sb + FK + (uint32_t)row * QROW_B + c16,
              K16 + (rb0 + row) * 2048 + hoff + c16);
    }
    CP_COMMIT;
    // ---- group 2: V(0) hi/lo ----
#pragma unroll
    for (int i = 0; i < 8; i++) {
        const char* g = (i < 4) ? Vh : Vl;
        const int row = ((i & 3) << 4) + rI;
        cpa16(sb + FVHI + (uint32_t)(i >> 2) * FT + (uint32_t)row * QROW_B + c16,
              g + (rb0 + row) * 2048 + hoff + c16);
    }
    CP_COMMIT;

    const int r8  = lane & 7;
    const int sel = lane >> 3;
    const uint32_t aOff = (uint32_t)(wid * 16 + (sel & 1) * 8 + r8) * QROW_B
                        + (uint32_t)((sel >> 1) * 16);
    const uint32_t bOff = (uint32_t)((sel >> 1) * 8 + r8) * QROW_B
                        + (uint32_t)((sel & 1) * 16);
    const uint32_t vOff = (uint32_t)((sel & 1) * 8 + r8) * QROW_B
                        + (uint32_t)((sel >> 1) * 16);

    float m_s[2] = {-1.0e30f, -1.0e30f};
    float l_s[2] = {0.f, 0.f};
    float o[8][4];
#pragma unroll
    for (int j = 0; j < 8; j++)
#pragma unroll
        for (int e = 0; e < 4; e++) o[j][e] = 0.f;

    const int NT = SEQ / 64;
    for (int kt = 0; kt < NT; kt++) {
        const size_t rn = rb0 + (size_t)(kt + 1) * 64;
        const bool more = (kt + 1 < NT);

        CP_WAIT1;
        __syncthreads();

        // ---- S = Q @ K^T (1-MMA, plain fp16) ----
        float s[8][4];
#pragma unroll
        for (int j = 0; j < 8; j++)
#pragma unroll
            for (int e = 0; e < 4; e++) s[j][e] = 0.f;

#pragma unroll
        for (int kc = 0; kc < 4; kc++) {
            const uint32_t kb = (uint32_t)kc * 32;
            uint32_t aq[4];
            ldsm4(aq, sb + FQ + aOff + kb);
#pragma unroll
            for (int j = 0; j < 4; j++) {
                uint32_t bk[4];
                ldsm4(bk, sb + FK + bOff + (uint32_t)(j * 16) * QROW_B + kb);
                MMA_F16(s[2 * j],     aq, bk[0], bk[1]);
                MMA_F16(s[2 * j + 1], aq, bk[2], bk[3]);
            }
        }

        __syncthreads();
        if (more) {             // prefetch K(kt+1) during softmax + PV
#pragma unroll
            for (int i = 0; i < 4; i++) {
                const int row = (i << 4) + rI;
                cpa16(sb + FK + (uint32_t)row * QROW_B + c16,
                      K16 + (rn + row) * 2048 + hoff + c16);
            }
            CP_COMMIT;
        }

        // ---- online softmax (log2 domain) ----
        float mx0 = s[0][0], mx1 = s[0][2];
#pragma unroll
        for (int j = 0; j < 8; j++) {
            mx0 = fmaxf(mx0, fmaxf(s[j][0], s[j][1]));
            mx1 = fmaxf(mx1, fmaxf(s[j][2], s[j][3]));
        }
        mx0 = fmaxf(mx0, __shfl_xor_sync(0xffffffffu, mx0, 1));
        mx0 = fmaxf(mx0, __shfl_xor_sync(0xffffffffu, mx0, 2));
        mx1 = fmaxf(mx1, __shfl_xor_sync(0xffffffffu, mx1, 1));
        mx1 = fmaxf(mx1, __shfl_xor_sync(0xffffffffu, mx1, 2));

        const float mn0 = fmaxf(m_s[0], mx0);
        const float mn1 = fmaxf(m_s[1], mx1);
        const float al0 = fexp2(m_s[0] - mn0);
        const float al1 = fexp2(m_s[1] - mn1);
        m_s[0] = mn0; m_s[1] = mn1;

        float sum0 = 0.f, sum1 = 0.f;
#pragma unroll
        for (int j = 0; j < 8; j++) {
            s[j][0] = fexp2(s[j][0] - mn0);
            s[j][1] = fexp2(s[j][1] - mn0);
            s[j][2] = fexp2(s[j][2] - mn1);
            s[j][3] = fexp2(s[j][3] - mn1);
            sum0 += s[j][0] + s[j][1];
            sum1 += s[j][2] + s[j][3];
        }
        sum0 += __shfl_xor_sync(0xffffffffu, sum0, 1);
        sum0 += __shfl_xor_sync(0xffffffffu, sum0, 2);
        sum1 += __shfl_xor_sync(0xffffffffu, sum1, 1);
        sum1 += __shfl_xor_sync(0xffffffffu, sum1, 2);
        l_s[0] = l_s[0] * al0 + sum0;
        l_s[1] = l_s[1] * al1 + sum1;

#pragma unroll
        for (int j = 0; j < 8; j++) {
            o[j][0] *= al0; o[j][1] *= al0;
            o[j][2] *= al1; o[j][3] *= al1;
        }

        if (more) { CP_WAIT1; } else { CP_WAIT0; }   // V(kt) arrived
        __syncthreads();

        // ---- PV: P plain fp16, V split (2-MMA) ----
#pragma unroll
        for (int kk = 0; kk < 4; kk++) {
            float* s0 = s[2 * kk];
            float* s1 = s[2 * kk + 1];
            uint32_t pa[4];
            pa[0] = pack_h2(s0[0], s0[1]);
            pa[1] = pack_h2(s0[2], s0[3]);
            pa[2] = pack_h2(s1[0], s1[1]);
            pa[3] = pack_h2(s1[2], s1[3]);
            const uint32_t rowk = (uint32_t)(kk * 16) * QROW_B;
#pragma unroll
            for (int j = 0; j < 4; j++) {
                uint32_t vh[4], vl[4];
                ldsm4t(vh, sb + FVHI + vOff + rowk + (uint32_t)(j * 32));
                ldsm4t(vl, sb + FVLO + vOff + rowk + (uint32_t)(j * 32));
                MMA_F16(o[2 * j],     pa, vh[0], vh[1]);
                MMA_F16(o[2 * j + 1], pa, vh[2], vh[3]);
                MMA_F16(o[2 * j],     pa, vl[0], vl[1]);
                MMA_F16(o[2 * j + 1], pa, vl[2], vl[3]);
            }
        }

        __syncthreads();
        if (more) {             // prefetch V(kt+1) during next S phase
#pragma unroll
            for (int i = 0; i < 8; i++) {
                const char* g = (i < 4) ? Vh : Vl;
                const int row = ((i & 3) << 4) + rI;
                cpa16(sb + FVHI + (uint32_t)(i >> 2) * FT
                         + (uint32_t)row * QROW_B + c16,
                      g + (rn + row) * 2048 + hoff + c16);
            }
            CP_COMMIT;
        }
    }

    // ---- epilogue: O plain fp16 ----
    const int g  = lane >> 2;
    const int c2 = (lane & 3) * 2;
    const float inv0 = 1.f / l_s[0];
    const float inv1 = 1.f / l_s[1];
    const size_t row0 = rq + (size_t)(wid * 16 + g);
#pragma unroll
    for (int j = 0; j < 8; j++) {
        size_t i0 = (row0 * DM + h * DH + j * 8 + c2) >> 1;
        size_t i1 = ((row0 + 8) * DM + h * DH + j * 8 + c2) >> 1;
        O16[i0] = pack_h2(o[j][0] * inv0, o[j][1] * inv0);
        O16[i1] = pack_h2(o[j][2] * inv1, o[j][3] * inv1);
    }
}

// ---------------------------------------------------------------------------
// Launch
// ---------------------------------------------------------------------------
extern "C" void kernel_launch(void* const* d_in, const int* in_sizes, int n_in,
                              void* d_out, int out_size) {
    const float* x   = (const float*)d_in[0];
    const float* src = (const float*)d_in[1];
    const float* Wq  = (const float*)d_in[2];
    const float* Wk  = (const float*)d_in[3];
    const float* Wv  = (const float*)d_in[4];
    const float* Wo  = (const float*)d_in[5];
    float* out = (float*)d_out;

    void *x16, *s16, *q16, *k16, *vh, *vl, *o16;
    void *wqh, *wql, *wkh, *wkl, *wvh, *wvl, *woh, *wol;
    cudaGetSymbolAddress(&x16, g_x16);
    cudaGetSymbolAddress(&s16, g_s16);
    cudaGetSymbolAddress(&q16, g_q16);
    cudaGetSymbolAddress(&k16, g_k16);
    cudaGetSymbolAddress(&vh, g_vh);   cudaGetSymbolAddress(&vl, g_vl);
    cudaGetSymbolAddress(&o16, g_o16);
    cudaGetSymbolAddress(&wqh, g_wqh); cudaGetSymbolAddress(&wql, g_wql);
    cudaGetSymbolAddress(&wkh, g_wkh); cudaGetSymbolAddress(&wkl, g_wkl);
    cudaGetSymbolAddress(&wvh, g_wvh); cudaGetSymbolAddress(&wvl, g_wvl);
    cudaGetSymbolAddress(&woh, g_woh); cudaGetSymbolAddress(&wol, g_wol);

    cudaFuncSetAttribute(gemm_qkv4, cudaFuncAttributeMaxDynamicSharedMemorySize, GSMEM);
    cudaFuncSetAttribute(gemm_out4, cudaFuncAttributeMaxDynamicSharedMemorySize, GSMEM);
    cudaFuncSetAttribute(flash_v7, cudaFuncAttributeMaxDynamicSharedMemorySize, FSMEM);

    const float qs = 0.125f * 1.4426950408889634f;
    const int n4x = M_TOT * DM / 4;
    const int n4w = DM * DM / 4;

    prep_rn16<<<n4x / 256, 256>>>((const float4*)x,   (uint2*)x16, n4x);
    prep_rn16<<<n4x / 256, 256>>>((const float4*)src, (uint2*)s16, n4x);
    prep_split16<<<n4w / 256, 256>>>((const float4*)Wq, (uint2*)wqh, (uint2*)wql, n4w, qs);
    prep_split16<<<n4w / 256, 256>>>((const float4*)Wk, (uint2*)wkh, (uint2*)wkl, n4w, 1.f);
    prep_split16<<<n4w / 256, 256>>>((const float4*)Wv, (uint2*)wvh, (uint2*)wvl, n4w, 1.f);
    prep_split16<<<n4w / 256, 256>>>((const float4*)Wo, (uint2*)woh, (uint2*)wol, n4w, 1.f);

    dim3 qkvgrid(DM / 128, M_TOT / 128, 3);
    gemm_qkv4<<<qkvgrid, 256, GSMEM>>>(
        (const char*)x16, (const char*)s16,
        (const char*)wqh, (const char*)wql, (const char*)wkh, (const char*)wkl,
        (const char*)wvh, (const char*)wvl,
        (uint32_t*)q16, (uint32_t*)k16, (uint32_t*)vh, (uint32_t*)vl);

    dim3 agrid(SEQ / 64, NH, BATCH);
    flash_v7<<<agrid, 128, FSMEM>>>(
        (const char*)q16, (const char*)k16,
        (const char*)vh, (const char*)vl, (uint32_t*)o16);

    dim3 ggrid(DM / 128, M_TOT / 128);
    gemm_out4<<<ggrid, 256, GSMEM>>>(
        (const char*)o16, (const char*)woh, (const char*)wol, out);
}

// round 11
// speedup vs baseline: 1.9034x; 1.3124x over previous
#include <cuda_runtime.h>
#include <cuda_fp16.h>
#include <cstdint>

#define DM     1024
#define NH     16
#define DH     64
#define SEQ    2048
#define BATCH  2
#define M_TOT  (BATCH * SEQ)   // 4096

// ---- fp16 scratch ----
__device__ __half g_x16[(size_t)M_TOT * DM];
__device__ __half g_s16[(size_t)M_TOT * DM];
__device__ __half g_q16[(size_t)M_TOT * DM];          // Q (pre-scaled)
__device__ __half g_k16[(size_t)M_TOT * DM];
__device__ __half g_v16[(size_t)M_TOT * DM];
__device__ __half g_o16[(size_t)M_TOT * DM];
__device__ __half g_wqh[DM * DM], g_wql[DM * DM];     // split (logit path)
__device__ __half g_wkh[DM * DM], g_wkl[DM * DM];     // split (logit path)
__device__ __half g_wv16[DM * DM];                    // plain (value path)
__device__ __half g_wo16[DM * DM];                    // plain (value path)

// ===========================================================================
// Helpers
// ===========================================================================
__device__ __forceinline__ uint32_t smem_u32(const void* p) {
    uint32_t a;
    asm("{ .reg .u64 t; cvta.to.shared.u64 t, %1; cvt.u32.u64 %0, t; }"
        : "=r"(a) : "l"(p));
    return a;
}
__device__ __forceinline__ void ldsm4(uint32_t* r, uint32_t addr) {
    asm volatile("ldmatrix.sync.aligned.m8n8.x4.shared.b16 {%0,%1,%2,%3}, [%4];"
                 : "=r"(r[0]), "=r"(r[1]), "=r"(r[2]), "=r"(r[3]) : "r"(addr));
}
__device__ __forceinline__ void ldsm4t(uint32_t* r, uint32_t addr) {
    asm volatile("ldmatrix.sync.aligned.m8n8.x4.trans.shared.b16 {%0,%1,%2,%3}, [%4];"
                 : "=r"(r[0]), "=r"(r[1]), "=r"(r[2]), "=r"(r[3]) : "r"(addr));
}
__device__ __forceinline__ void cpa16(uint32_t saddr, const void* gaddr) {
    asm volatile("cp.async.cg.shared.global [%0], [%1], 16;"
                 :: "r"(saddr), "l"(gaddr) : "memory");
}
#define CP_COMMIT asm volatile("cp.async.commit_group;" ::: "memory")
#define CP_WAIT0  asm volatile("cp.async.wait_group 0;" ::: "memory")
#define CP_WAIT1  asm volatile("cp.async.wait_group 1;" ::: "memory")

#define MMA_F16(d, a, b0, b1) \
    asm volatile("mma.sync.aligned.m16n8k16.row.col.f32.f16.f16.f32 " \
                 "{%0,%1,%2,%3},{%4,%5,%6,%7},{%8,%9},{%0,%1,%2,%3};" \
                 : "+f"((d)[0]), "+f"((d)[1]), "+f"((d)[2]), "+f"((d)[3]) \
                 : "r"((a)[0]), "r"((a)[1]), "r"((a)[2]), "r"((a)[3]), \
                   "r"(b0), "r"(b1))

__device__ __forceinline__ uint32_t pack_h2(float x, float y) {
    __half2 p = __floats2half2_rn(x, y);
    return *reinterpret_cast<uint32_t*>(&p);
}
__device__ __forceinline__ void split2f(float x, float y,
                                        uint32_t& h, uint32_t& l) {
    float hx = __half2float(__float2half_rn(x));
    float hy = __half2float(__float2half_rn(y));
    h = pack_h2(hx, hy);
    l = pack_h2(x - hx, y - hy);
}
__device__ __forceinline__ float fexp2(float x) {
    x = fmaxf(x, -126.0f);
    float z = x + 12582912.0f;
    float f = x - (z - 12582912.0f);
    float p = 0.0013333558f;
    p = fmaf(p, f, 0.0096181291f);
    p = fmaf(p, f, 0.0555041087f);
    p = fmaf(p, f, 0.2402265069f);
    p = fmaf(p, f, 0.6931471806f);
    p = fmaf(p, f, 1.0f);
    return __uint_as_float(__float_as_uint(p) + (__float_as_uint(z) << 23));
}

// ===========================================================================
// Prep kernels
// ===========================================================================
__global__ __launch_bounds__(256) void prep_split16(const float4* __restrict__ in,
                                                    uint2* __restrict__ hi,
                                                    uint2* __restrict__ lo,
                                                    int n4, float scale) {
    int i = blockIdx.x * blockDim.x + threadIdx.x;
    if (i >= n4) return;
    float4 v = in[i];
    v.x *= scale; v.y *= scale; v.z *= scale; v.w *= scale;
    uint32_t h0, l0, h1, l1;
    split2f(v.x, v.y, h0, l0);
    split2f(v.z, v.w, h1, l1);
    hi[i] = make_uint2(h0, h1);
    lo[i] = make_uint2(l0, l1);
}
__global__ __launch_bounds__(256) void prep_rn16(const float4* __restrict__ in,
                                                 uint2* __restrict__ out, int n4) {
    int i = blockIdx.x * blockDim.x + threadIdx.x;
    if (i >= n4) return;
    float4 v = in[i];
    out[i] = make_uint2(pack_h2(v.x, v.y), pack_h2(v.z, v.w));
}

// ===========================================================================
// fp16 GEMM cores: Y = A @ B^T, 128x128 CTA tile, KC=32, cp.async dbl-buffer.
// core2: 2-MMA (A * (Bh + Bl))       [logit-path projections]
// core1: 1-MMA (A * B)               [value-path projections]
// ===========================================================================
#define LDT2 80
#define TILE_BYTES (128 * LDT2)          // 10240
#define STG2 (3 * TILE_BYTES)            // A, Bh, Bl
#define STG1 (2 * TILE_BYTES)            // A, B
#define GSMEM2 (2 * STG2)                // 61440
#define GSMEM1 (2 * STG1)                // 40960

template<int NB>   // NB = number of B tiles (1 or 2)
__device__ __forceinline__ void g_issue(uint32_t ss, const char* A,
                                        const char* Bh, const char* Bl,
                                        int m0, int n0, uint32_t k0b, int t) {
#pragma unroll
    for (int i = 0; i < 2 * (1 + NB); i++) {
        const char* g = (i < 2) ? A : (i < 4) ? Bh : Bl;
        const uint32_t slot = (uint32_t)(i >> 1);
        const int r0 = (i < 2) ? m0 : n0;
        const int row = ((i & 1) << 6) + (t >> 2);
        const uint32_t c16 = (uint32_t)(t & 3) << 4;
        cpa16(ss + slot * (uint32_t)TILE_BYTES + (uint32_t)row * LDT2 + c16,
              g + (size_t)(r0 + row) * 2048 + k0b + c16);
    }
}

template<int NB>
__device__ __forceinline__ void gemm_core(const char* A, const char* Bh,
                                          const char* Bl, uint32_t sbase,
                                          int m0, int n0,
                                          float (&acc)[4][4][4]) {
    const int t    = threadIdx.x;
    const int lane = t & 31;
    const int wid  = t >> 5;
    const int wm   = wid & 1;
    const int wn   = wid >> 1;
    const uint32_t STG = (uint32_t)((1 + NB) * TILE_BYTES);

#pragma unroll
    for (int mi = 0; mi < 4; mi++)
#pragma unroll
        for (int ni = 0; ni < 4; ni++)
#pragma unroll
            for (int e = 0; e < 4; e++) acc[mi][ni][e] = 0.f;

    const int r8  = lane & 7;
    const int sel = lane >> 3;
    const uint32_t aRowOff = (uint32_t)(wm * 64 + (sel & 1) * 8 + r8) * LDT2
                           + (uint32_t)((sel >> 1) * 8) * 2;
    const uint32_t bRowOff = (uint32_t)(wn * 32 + (sel >> 1) * 8 + r8) * LDT2
                           + (uint32_t)((sel & 1) * 8) * 2;

    auto compute = [&](uint32_t sb) {
        const uint32_t sA  = sb;
        const uint32_t sB0 = sb + TILE_BYTES;
        const uint32_t sB1 = sb + 2 * TILE_BYTES;
#pragma unroll
        for (int ks = 0; ks < 2; ks++) {
            const uint32_t kb = (uint32_t)ks * 32;
            uint32_t ah[4][4];
#pragma unroll
            for (int mi = 0; mi < 4; mi++)
                ldsm4(ah[mi], sA + aRowOff + (uint32_t)(mi * 16) * LDT2 + kb);
            uint32_t bh[2][4];
#pragma unroll
            for (int np = 0; np < 2; np++)
                ldsm4(bh[np], sB0 + bRowOff + (uint32_t)(np * 16) * LDT2 + kb);
#pragma unroll
            for (int mi = 0; mi < 4; mi++)
#pragma unroll
                for (int ni = 0; ni < 4; ni++)
                    MMA_F16(acc[mi][ni], ah[mi],
                            bh[ni >> 1][(ni & 1) * 2],
                            bh[ni >> 1][(ni & 1) * 2 + 1]);
            if (NB == 2) {
                uint32_t bl[2][4];
#pragma unroll
                for (int np = 0; np < 2; np++)
                    ldsm4(bl[np], sB1 + bRowOff + (uint32_t)(np * 16) * LDT2 + kb);
#pragma unroll
                for (int mi = 0; mi < 4; mi++)
#pragma unroll
                    for (int ni = 0; ni < 4; ni++)
                        MMA_F16(acc[mi][ni], ah[mi],
                                bl[ni >> 1][(ni & 1) * 2],
                                bl[ni >> 1][(ni & 1) * 2 + 1]);
            }
        }
    };

    g_issue<NB>(sbase, A, Bh, Bl, m0, n0, 0u, t);
    CP_COMMIT;

    const int NCHUNK = DM / 32;
    for (int chunk = 0; chunk < NCHUNK; chunk++) {
        const int s = chunk & 1;
        CP_WAIT0;
        __syncthreads();
        if (chunk + 1 < NCHUNK) {
            g_issue<NB>(sbase + (uint32_t)(s ^ 1) * STG,
                        A, Bh, Bl, m0, n0, (uint32_t)(chunk + 1) * 64, t);
            CP_COMMIT;
        }
        compute(sbase + (uint32_t)s * STG);
    }
}

// QKV projections: z=0 Q (2-MMA, split Wq), z=1 K (2-MMA, split Wk),
// z=2 V (1-MMA, plain Wv). All outputs plain fp16.
__global__ __launch_bounds__(256, 2)
void gemm_qkv5(const char* x16, const char* s16,
               const char* wqh, const char* wql, const char* wkh, const char* wkl,
               const char* wv16,
               uint32_t* q16, uint32_t* k16, uint32_t* v16) {
    extern __shared__ __align__(16) char sm[];
    const int z  = blockIdx.z;
    const int m0 = blockIdx.y * 128;
    const int n0 = blockIdx.x * 128;

    float acc[4][4][4];
    if (z == 0)      gemm_core<2>(x16, wqh, wql, smem_u32(sm), m0, n0, acc);
    else if (z == 1) gemm_core<2>(s16, wkh, wkl, smem_u32(sm), m0, n0, acc);
    else             gemm_core<1>(s16, wv16, wv16, smem_u32(sm), m0, n0, acc);

    uint32_t* Y = (z == 0) ? q16 : (z == 1 ? k16 : v16);

    const int lane = threadIdx.x & 31;
    const int wid  = threadIdx.x >> 5;
    const int wm   = wid & 1, wn = wid >> 1;
    const int g  = lane >> 2;
    const int c2 = (lane & 3) * 2;
#pragma unroll
    for (int mi = 0; mi < 4; mi++) {
#pragma unroll
        for (int ni = 0; ni < 4; ni++) {
            int row = m0 + wm * 64 + mi * 16 + g;
            int col = n0 + wn * 32 + ni * 8 + c2;
            Y[((size_t)row * DM + col) >> 1]       = pack_h2(acc[mi][ni][0], acc[mi][ni][1]);
            Y[((size_t)(row + 8) * DM + col) >> 1] = pack_h2(acc[mi][ni][2], acc[mi][ni][3]);
        }
    }
}

// Output projection: O @ Wo^T (1-MMA), fp32 epilogue.
__global__ __launch_bounds__(256, 2)
void gemm_out5(const char* o16, const char* wo16, float* __restrict__ Y) {
    extern __shared__ __align__(16) char sm[];
    const int m0 = blockIdx.y * 128;
    const int n0 = blockIdx.x * 128;

    float acc[4][4][4];
    gemm_core<1>(o16, wo16, wo16, smem_u32(sm), m0, n0, acc);

    const int lane = threadIdx.x & 31;
    const int wid  = threadIdx.x >> 5;
    const int wm   = wid & 1, wn = wid >> 1;
    const int g  = lane >> 2;
    const int c2 = (lane & 3) * 2;
#pragma unroll
    for (int mi = 0; mi < 4; mi++) {
#pragma unroll
        for (int ni = 0; ni < 4; ni++) {
            int row = m0 + wm * 64 + mi * 16 + g;
            int col = n0 + wn * 32 + ni * 8 + c2;
            float2 v0 = {acc[mi][ni][0], acc[mi][ni][1]};
            float2 v1 = {acc[mi][ni][2], acc[mi][ni][3]};
            *(float2*)(Y + (size_t)row * DM + col)       = v0;
            *(float2*)(Y + (size_t)(row + 8) * DM + col) = v1;
        }
    }
}

// ===========================================================================
// Flash attention v8 (fp16): QK 1-MMA, PV 1-MMA (all plain fp16 operands).
// 128 threads / 64 q-rows, 4 CTAs/SM, cp.async K/V overlap.
// ===========================================================================
#define QROW_B 144
#define FT     9216
#define FQ     0
#define FK     (1 * FT)
#define FV     (2 * FT)
#define FSMEM  (3 * FT)                  // 27648

__global__ __launch_bounds__(128, 4)
void flash_v8(const char* Q16, const char* K16, const char* V16,
              uint32_t* O16) {
    extern __shared__ __align__(16) char fsm[];
    const uint32_t sb = smem_u32(fsm);

    const int t    = threadIdx.x;
    const int lane = t & 31;
    const int wid  = t >> 5;
    const int b    = blockIdx.z;
    const int h    = blockIdx.y;
    const int q0   = blockIdx.x * 64;
    const size_t rq  = (size_t)(b * SEQ + q0);
    const size_t rb0 = (size_t)(b * SEQ);
    const uint32_t hoff = (uint32_t)h * 128u;

    const int rI  = t >> 3;
    const uint32_t c16 = (uint32_t)(t & 7) << 4;

    // group 1: Q + K(0)
#pragma unroll
    for (int i = 0; i < 4; i++) {
        const int row = (i << 4) + rI;
        cpa16(sb + FQ + (uint32_t)row * QROW_B + c16,
              Q16 + (rq + row) * 2048 + hoff + c16);
    }
#pragma unroll
    for (int i = 0; i < 4; i++) {
        const int row = (i << 4) + rI;
        cpa16(sb + FK + (uint32_t)row * QROW_B + c16,
              K16 + (rb0 + row) * 2048 + hoff + c16);
    }
    CP_COMMIT;
    // group 2: V(0)
#pragma unroll
    for (int i = 0; i < 4; i++) {
        const int row = (i << 4) + rI;
        cpa16(sb + FV + (uint32_t)row * QROW_B + c16,
              V16 + (rb0 + row) * 2048 + hoff + c16);
    }
    CP_COMMIT;

    const int r8  = lane & 7;
    const int sel = lane >> 3;
    const uint32_t aOff = (uint32_t)(wid * 16 + (sel & 1) * 8 + r8) * QROW_B
                        + (uint32_t)((sel >> 1) * 16);
    const uint32_t bOff = (uint32_t)((sel >> 1) * 8 + r8) * QROW_B
                        + (uint32_t)((sel & 1) * 16);
    const uint32_t vOff = (uint32_t)((sel & 1) * 8 + r8) * QROW_B
                        + (uint32_t)((sel >> 1) * 16);

    float m_s[2] = {-1.0e30f, -1.0e30f};
    float l_s[2] = {0.f, 0.f};
    float o[8][4];
#pragma unroll
    for (int j = 0; j < 8; j++)
#pragma unroll
        for (int e = 0; e < 4; e++) o[j][e] = 0.f;

    const int NT = SEQ / 64;
    for (int kt = 0; kt < NT; kt++) {
        const size_t rn = rb0 + (size_t)(kt + 1) * 64;
        const bool more = (kt + 1 < NT);

        CP_WAIT1;
        __syncthreads();

        // S = Q @ K^T (1-MMA)
        float s[8][4];
#pragma unroll
        for (int j = 0; j < 8; j++)
#pragma unroll
            for (int e = 0; e < 4; e++) s[j][e] = 0.f;

#pragma unroll
        for (int kc = 0; kc < 4; kc++) {
            const uint32_t kb = (uint32_t)kc * 32;
            uint32_t aq[4];
            ldsm4(aq, sb + FQ + aOff + kb);
#pragma unroll
            for (int j = 0; j < 4; j++) {
                uint32_t bk[4];
                ldsm4(bk, sb + FK + bOff + (uint32_t)(j * 16) * QROW_B + kb);
                MMA_F16(s[2 * j],     aq, bk[0], bk[1]);
                MMA_F16(s[2 * j + 1], aq, bk[2], bk[3]);
            }
        }

        __syncthreads();
        if (more) {             // prefetch K(kt+1)
#pragma unroll
            for (int i = 0; i < 4; i++) {
                const int row = (i << 4) + rI;
                cpa16(sb + FK + (uint32_t)row * QROW_B + c16,
                      K16 + (rn + row) * 2048 + hoff + c16);
            }
            CP_COMMIT;
        }

        // online softmax (log2 domain)
        float mx0 = s[0][0], mx1 = s[0][2];
#pragma unroll
        for (int j = 0; j < 8; j++) {
            mx0 = fmaxf(mx0, fmaxf(s[j][0], s[j][1]));
            mx1 = fmaxf(mx1, fmaxf(s[j][2], s[j][3]));
        }
        mx0 = fmaxf(mx0, __shfl_xor_sync(0xffffffffu, mx0, 1));
        mx0 = fmaxf(mx0, __shfl_xor_sync(0xffffffffu, mx0, 2));
        mx1 = fmaxf(mx1, __shfl_xor_sync(0xffffffffu, mx1, 1));
        mx1 = fmaxf(mx1, __shfl_xor_sync(0xffffffffu, mx1, 2));

        const float mn0 = fmaxf(m_s[0], mx0);
        const float mn1 = fmaxf(m_s[1], mx1);
        const float al0 = fexp2(m_s[0] - mn0);
        const float al1 = fexp2(m_s[1] - mn1);
        m_s[0] = mn0; m_s[1] = mn1;

        float sum0 = 0.f, sum1 = 0.f;
#pragma unroll
        for (int j = 0; j < 8; j++) {
            s[j][0] = fexp2(s[j][0] - mn0);
            s[j][1] = fexp2(s[j][1] - mn0);
            s[j][2] = fexp2(s[j][2] - mn1);
            s[j][3] = fexp2(s[j][3] - mn1);
            sum0 += s[j][0] + s[j][1];
            sum1 += s[j][2] + s[j][3];
        }
        sum0 += __shfl_xor_sync(0xffffffffu, sum0, 1);
        sum0 += __shfl_xor_sync(0xffffffffu, sum0, 2);
        sum1 += __shfl_xor_sync(0xffffffffu, sum1, 1);
        sum1 += __shfl_xor_sync(0xffffffffu, sum1, 2);
        l_s[0] = l_s[0] * al0 + sum0;
        l_s[1] = l_s[1] * al1 + sum1;

#pragma unroll
        for (int j = 0; j < 8; j++) {
            o[j][0] *= al0; o[j][1] *= al0;
            o[j][2] *= al1; o[j][3] *= al1;
        }

        if (more) { CP_WAIT1; } else { CP_WAIT0; }   // V(kt) arrived
        __syncthreads();

        // PV (1-MMA, plain fp16)
#pragma unroll
        for (int kk = 0; kk < 4; kk++) {
            float* s0 = s[2 * kk];
            float* s1 = s[2 * kk + 1];
            uint32_t pa[4];
            pa[0] = pack_h2(s0[0], s0[1]);
            pa[1] = pack_h2(s0[2], s0[3]);
            pa[2] = pack_h2(s1[0], s1[1]);
            pa[3] = pack_h2(s1[2], s1[3]);
            const uint32_t rowk = (uint32_t)(kk * 16) * QROW_B;
#pragma unroll
            for (int j = 0; j < 4; j++) {
                uint32_t vv[4];
                ldsm4t(vv, sb + FV + vOff + rowk + (uint32_t)(j * 32));
                MMA_F16(o[2 * j],     pa, vv[0], vv[1]);
                MMA_F16(o[2 * j + 1], pa, vv[2], vv[3]);
            }
        }

        __syncthreads();
        if (more) {             // prefetch V(kt+1)
#pragma unroll
            for (int i = 0; i < 4; i++) {
                const int row = (i << 4) + rI;
                cpa16(sb + FV + (uint32_t)row * QROW_B + c16,
                      V16 + (rn + row) * 2048 + hoff + c16);
            }
            CP_COMMIT;
        }
    }

    // epilogue: O plain fp16
    const int g  = lane >> 2;
    const int c2 = (lane & 3) * 2;
    const float inv0 = 1.f / l_s[0];
    const float inv1 = 1.f / l_s[1];
    const size_t row0 = rq + (size_t)(wid * 16 + g);
#pragma unroll
    for (int j = 0; j < 8; j++) {
        size_t i0 = (row0 * DM + h * DH + j * 8 + c2) >> 1;
        size_t i1 = ((row0 + 8) * DM + h * DH + j * 8 + c2) >> 1;
        O16[i0] = pack_h2(o[j][0] * inv0, o[j][1] * inv0);
        O16[i1] = pack_h2(o[j][2] * inv1, o[j][3] * inv1);
    }
}

// ---------------------------------------------------------------------------
// Launch
// ---------------------------------------------------------------------------
extern "C" void kernel_launch(void* const* d_in, const int* in_sizes, int n_in,
                              void* d_out, int out_size) {
    const float* x   = (const float*)d_in[0];
    const float* src = (const float*)d_in[1];
    const float* Wq  = (const float*)d_in[2];
    const float* Wk  = (const float*)d_in[3];
    const float* Wv  = (const float*)d_in[4];
    const float* Wo  = (const float*)d_in[5];
    float* out = (float*)d_out;

    void *x16, *s16, *q16, *k16, *v16, *o16;
    void *wqh, *wql, *wkh, *wkl, *wv16, *wo16;
    cudaGetSymbolAddress(&x16, g_x16);
    cudaGetSymbolAddress(&s16, g_s16);
    cudaGetSymbolAddress(&q16, g_q16);
    cudaGetSymbolAddress(&k16, g_k16);
    cudaGetSymbolAddress(&v16, g_v16);
    cudaGetSymbolAddress(&o16, g_o16);
    cudaGetSymbolAddress(&wqh, g_wqh); cudaGetSymbolAddress(&wql, g_wql);
    cudaGetSymbolAddress(&wkh, g_wkh); cudaGetSymbolAddress(&wkl, g_wkl);
    cudaGetSymbolAddress(&wv16, g_wv16);
    cudaGetSymbolAddress(&wo16, g_wo16);

    cudaFuncSetAttribute(gemm_qkv5, cudaFuncAttributeMaxDynamicSharedMemorySize, GSMEM2);
    cudaFuncSetAttribute(gemm_out5, cudaFuncAttributeMaxDynamicSharedMemorySize, GSMEM1);
    cudaFuncSetAttribute(flash_v8, cudaFuncAttributeMaxDynamicSharedMemorySize, FSMEM);

    const float qs = 0.125f * 1.4426950408889634f;
    const int n4x = M_TOT * DM / 4;
    const int n4w = DM * DM / 4;

    prep_rn16<<<n4x / 256, 256>>>((const float4*)x,   (uint2*)x16, n4x);
    prep_rn16<<<n4x / 256, 256>>>((const float4*)src, (uint2*)s16, n4x);
    prep_split16<<<n4w / 256, 256>>>((const float4*)Wq, (uint2*)wqh, (uint2*)wql, n4w, qs);
    prep_split16<<<n4w / 256, 256>>>((const float4*)Wk, (uint2*)wkh, (uint2*)wkl, n4w, 1.f);
    prep_rn16<<<n4w / 256, 256>>>((const float4*)Wv, (uint2*)wv16, n4w);
    prep_rn16<<<n4w / 256, 256>>>((const float4*)Wo, (uint2*)wo16, n4w);

    dim3 qkvgrid(DM / 128, M_TOT / 128, 3);
    gemm_qkv5<<<qkvgrid, 256, GSMEM2>>>(
        (const char*)x16, (const char*)s16,
        (const char*)wqh, (const char*)wql, (const char*)wkh, (const char*)wkl,
        (const char*)wv16,
        (uint32_t*)q16, (uint32_t*)k16, (uint32_t*)v16);

    dim3 agrid(SEQ / 64, NH, BATCH);
    flash_v8<<<agrid, 128, FSMEM>>>(
        (const char*)q16, (const char*)k16, (const char*)v16, (uint32_t*)o16);

    dim3 ggrid(DM / 128, M_TOT / 128);
    gemm_out5<<<ggrid, 256, GSMEM1>>>(
        (const char*)o16, (const char*)wo16, out);
}

// round 12
// speedup vs baseline: 1.9542x; 1.0267x over previous
#include <cuda_runtime.h>
#include <cuda_fp16.h>
#include <cstdint>

#define DM     1024
#define NH     16
#define DH     64
#define SEQ    2048
#define BATCH  2
#define M_TOT  (BATCH * SEQ)   // 4096

// ---- fp16 scratch ----
__device__ __half g_x16[(size_t)M_TOT * DM];
__device__ __half g_s16[(size_t)M_TOT * DM];
__device__ __half g_q16[(size_t)M_TOT * DM];          // Q (pre-scaled)
__device__ __half g_k16[(size_t)M_TOT * DM];
__device__ __half g_v16[(size_t)M_TOT * DM];
__device__ __half g_o16[(size_t)M_TOT * DM];
__device__ __half g_wqh[DM * DM], g_wql[DM * DM];     // split (logit path)
__device__ __half g_wkh[DM * DM], g_wkl[DM * DM];     // split (logit path)
__device__ __half g_wv16[DM * DM];                    // plain (value path)
__device__ __half g_wo16[DM * DM];                    // plain (value path)

// ===========================================================================
// Helpers
// ===========================================================================
__device__ __forceinline__ uint32_t smem_u32(const void* p) {
    uint32_t a;
    asm("{ .reg .u64 t; cvta.to.shared.u64 t, %1; cvt.u32.u64 %0, t; }"
        : "=r"(a) : "l"(p));
    return a;
}
__device__ __forceinline__ void ldsm4(uint32_t* r, uint32_t addr) {
    asm volatile("ldmatrix.sync.aligned.m8n8.x4.shared.b16 {%0,%1,%2,%3}, [%4];"
                 : "=r"(r[0]), "=r"(r[1]), "=r"(r[2]), "=r"(r[3]) : "r"(addr));
}
__device__ __forceinline__ void ldsm4t(uint32_t* r, uint32_t addr) {
    asm volatile("ldmatrix.sync.aligned.m8n8.x4.trans.shared.b16 {%0,%1,%2,%3}, [%4];"
                 : "=r"(r[0]), "=r"(r[1]), "=r"(r[2]), "=r"(r[3]) : "r"(addr));
}
__device__ __forceinline__ void cpa16(uint32_t saddr, const void* gaddr) {
    asm volatile("cp.async.cg.shared.global [%0], [%1], 16;"
                 :: "r"(saddr), "l"(gaddr) : "memory");
}
#define CP_COMMIT asm volatile("cp.async.commit_group;" ::: "memory")
#define CP_WAIT0  asm volatile("cp.async.wait_group 0;" ::: "memory")

#define MMA_F16(d, a, b0, b1) \
    asm volatile("mma.sync.aligned.m16n8k16.row.col.f32.f16.f16.f32 " \
                 "{%0,%1,%2,%3},{%4,%5,%6,%7},{%8,%9},{%0,%1,%2,%3};" \
                 : "+f"((d)[0]), "+f"((d)[1]), "+f"((d)[2]), "+f"((d)[3]) \
                 : "r"((a)[0]), "r"((a)[1]), "r"((a)[2]), "r"((a)[3]), \
                   "r"(b0), "r"(b1))

__device__ __forceinline__ uint32_t pack_h2(float x, float y) {
    __half2 p = __floats2half2_rn(x, y);
    return *reinterpret_cast<uint32_t*>(&p);
}
__device__ __forceinline__ void split2f(float x, float y,
                                        uint32_t& h, uint32_t& l) {
    float hx = __half2float(__float2half_rn(x));
    float hy = __half2float(__float2half_rn(y));
    h = pack_h2(hx, hy);
    l = pack_h2(x - hx, y - hy);
}
__device__ __forceinline__ float fexp2(float x) {
    x = fmaxf(x, -126.0f);
    float z = x + 12582912.0f;
    float f = x - (z - 12582912.0f);
    float p = 0.0013333558f;
    p = fmaf(p, f, 0.0096181291f);
    p = fmaf(p, f, 0.0555041087f);
    p = fmaf(p, f, 0.2402265069f);
    p = fmaf(p, f, 0.6931471806f);
    p = fmaf(p, f, 1.0f);
    return __uint_as_float(__float_as_uint(p) + (__float_as_uint(z) << 23));
}

// ===========================================================================
// Fused prep: all fp32->fp16 conversions/splits in ONE launch.
// Regions (in float4 units): x | src | Wq(split,qs) | Wk(split) | Wv | Wo
// ===========================================================================
#define N4X (M_TOT * DM / 4)      // 1048576
#define N4W (DM * DM / 4)         // 262144
#define N4TOT (2 * N4X + 4 * N4W) // 3145728

__global__ __launch_bounds__(256)
void prep_all(const float4* __restrict__ x,   const float4* __restrict__ src,
              const float4* __restrict__ Wq,  const float4* __restrict__ Wk,
              const float4* __restrict__ Wv,  const float4* __restrict__ Wo,
              uint2* __restrict__ x16,  uint2* __restrict__ s16,
              uint2* __restrict__ wqh,  uint2* __restrict__ wql,
              uint2* __restrict__ wkh,  uint2* __restrict__ wkl,
              uint2* __restrict__ wv16, uint2* __restrict__ wo16,
              float qs) {
    int i = blockIdx.x * blockDim.x + threadIdx.x;
    if (i >= N4TOT) return;

    if (i < 2 * N4X) {                 // plain: x / src
        const bool isx = (i < N4X);
        int j = isx ? i : i - N4X;
        float4 v = (isx ? x : src)[j];
        (isx ? x16 : s16)[j] = make_uint2(pack_h2(v.x, v.y), pack_h2(v.z, v.w));
        return;
    }
    int j = i - 2 * N4X;
    if (j < 2 * N4W) {                 // split: Wq (scaled) / Wk
        const bool isq = (j < N4W);
        int k = isq ? j : j - N4W;
        float4 v = (isq ? Wq : Wk)[k];
        if (isq) { v.x *= qs; v.y *= qs; v.z *= qs; v.w *= qs; }
        uint32_t h0, l0, h1, l1;
        split2f(v.x, v.y, h0, l0);
        split2f(v.z, v.w, h1, l1);
        (isq ? wqh : wkh)[k] = make_uint2(h0, h1);
        (isq ? wql : wkl)[k] = make_uint2(l0, l1);
        return;
    }
    j -= 2 * N4W;                      // plain: Wv / Wo
    const bool isv = (j < N4W);
    int k = isv ? j : j - N4W;
    float4 v = (isv ? Wv : Wo)[k];
    (isv ? wv16 : wo16)[k] = make_uint2(pack_h2(v.x, v.y), pack_h2(v.z, v.w));
}

// ===========================================================================
// fp16 GEMM cores (unchanged from R11): Y = A @ B^T, 128x128 tile, KC=32.
// ===========================================================================
#define LDT2 80
#define TILE_BYTES (128 * LDT2)
#define GSMEM2 (2 * 3 * TILE_BYTES)      // 61440
#define GSMEM1 (2 * 2 * TILE_BYTES)      // 40960

template<int NB>
__device__ __forceinline__ void g_issue(uint32_t ss, const char* A,
                                        const char* Bh, const char* Bl,
                                        int m0, int n0, uint32_t k0b, int t) {
#pragma unroll
    for (int i = 0; i < 2 * (1 + NB); i++) {
        const char* g = (i < 2) ? A : (i < 4) ? Bh : Bl;
        const uint32_t slot = (uint32_t)(i >> 1);
        const int r0 = (i < 2) ? m0 : n0;
        const int row = ((i & 1) << 6) + (t >> 2);
        const uint32_t c16 = (uint32_t)(t & 3) << 4;
        cpa16(ss + slot * (uint32_t)TILE_BYTES + (uint32_t)row * LDT2 + c16,
              g + (size_t)(r0 + row) * 2048 + k0b + c16);
    }
}

template<int NB>
__device__ __forceinline__ void gemm_core(const char* A, const char* Bh,
                                          const char* Bl, uint32_t sbase,
                                          int m0, int n0,
                                          float (&acc)[4][4][4]) {
    const int t    = threadIdx.x;
    const int lane = t & 31;
    const int wid  = t >> 5;
    const int wm   = wid & 1;
    const int wn   = wid >> 1;
    const uint32_t STG = (uint32_t)((1 + NB) * TILE_BYTES);

#pragma unroll
    for (int mi = 0; mi < 4; mi++)
#pragma unroll
        for (int ni = 0; ni < 4; ni++)
#pragma unroll
            for (int e = 0; e < 4; e++) acc[mi][ni][e] = 0.f;

    const int r8  = lane & 7;
    const int sel = lane >> 3;
    const uint32_t aRowOff = (uint32_t)(wm * 64 + (sel & 1) * 8 + r8) * LDT2
                           + (uint32_t)((sel >> 1) * 8) * 2;
    const uint32_t bRowOff = (uint32_t)(wn * 32 + (sel >> 1) * 8 + r8) * LDT2
                           + (uint32_t)((sel & 1) * 8) * 2;

    auto compute = [&](uint32_t sb) {
        const uint32_t sA  = sb;
        const uint32_t sB0 = sb + TILE_BYTES;
        const uint32_t sB1 = sb + 2 * TILE_BYTES;
#pragma unroll
        for (int ks = 0; ks < 2; ks++) {
            const uint32_t kb = (uint32_t)ks * 32;
            uint32_t ah[4][4];
#pragma unroll
            for (int mi = 0; mi < 4; mi++)
                ldsm4(ah[mi], sA + aRowOff + (uint32_t)(mi * 16) * LDT2 + kb);
            uint32_t bh[2][4];
#pragma unroll
            for (int np = 0; np < 2; np++)
                ldsm4(bh[np], sB0 + bRowOff + (uint32_t)(np * 16) * LDT2 + kb);
#pragma unroll
            for (int mi = 0; mi < 4; mi++)
#pragma unroll
                for (int ni = 0; ni < 4; ni++)
                    MMA_F16(acc[mi][ni], ah[mi],
                            bh[ni >> 1][(ni & 1) * 2],
                            bh[ni >> 1][(ni & 1) * 2 + 1]);
            if (NB == 2) {
                uint32_t bl[2][4];
#pragma unroll
                for (int np = 0; np < 2; np++)
                    ldsm4(bl[np], sB1 + bRowOff + (uint32_t)(np * 16) * LDT2 + kb);
#pragma unroll
                for (int mi = 0; mi < 4; mi++)
#pragma unroll
                    for (int ni = 0; ni < 4; ni++)
                        MMA_F16(acc[mi][ni], ah[mi],
                                bl[ni >> 1][(ni & 1) * 2],
                                bl[ni >> 1][(ni & 1) * 2 + 1]);
            }
        }
    };

    g_issue<NB>(sbase, A, Bh, Bl, m0, n0, 0u, t);
    CP_COMMIT;

    const int NCHUNK = DM / 32;
    for (int chunk = 0; chunk < NCHUNK; chunk++) {
        const int s = chunk & 1;
        CP_WAIT0;
        __syncthreads();
        if (chunk + 1 < NCHUNK) {
            g_issue<NB>(sbase + (uint32_t)(s ^ 1) * STG,
                        A, Bh, Bl, m0, n0, (uint32_t)(chunk + 1) * 64, t);
            CP_COMMIT;
        }
        compute(sbase + (uint32_t)s * STG);
    }
}

__global__ __launch_bounds__(256, 2)
void gemm_qkv5(const char* x16, const char* s16,
               const char* wqh, const char* wql, const char* wkh, const char* wkl,
               const char* wv16,
               uint32_t* q16, uint32_t* k16, uint32_t* v16) {
    extern __shared__ __align__(16) char sm[];
    const int z  = blockIdx.z;
    const int m0 = blockIdx.y * 128;
    const int n0 = blockIdx.x * 128;

    float acc[4][4][4];
    if (z == 0)      gemm_core<2>(x16, wqh, wql, smem_u32(sm), m0, n0, acc);
    else if (z == 1) gemm_core<2>(s16, wkh, wkl, smem_u32(sm), m0, n0, acc);
    else             gemm_core<1>(s16, wv16, wv16, smem_u32(sm), m0, n0, acc);

    uint32_t* Y = (z == 0) ? q16 : (z == 1 ? k16 : v16);

    const int lane = threadIdx.x & 31;
    const int wid  = threadIdx.x >> 5;
    const int wm   = wid & 1, wn = wid >> 1;
    const int g  = lane >> 2;
    const int c2 = (lane & 3) * 2;
#pragma unroll
    for (int mi = 0; mi < 4; mi++) {
#pragma unroll
        for (int ni = 0; ni < 4; ni++) {
            int row = m0 + wm * 64 + mi * 16 + g;
            int col = n0 + wn * 32 + ni * 8 + c2;
            Y[((size_t)row * DM + col) >> 1]       = pack_h2(acc[mi][ni][0], acc[mi][ni][1]);
            Y[((size_t)(row + 8) * DM + col) >> 1] = pack_h2(acc[mi][ni][2], acc[mi][ni][3]);
        }
    }
}

__global__ __launch_bounds__(256, 2)
void gemm_out5(const char* o16, const char* wo16, float* __restrict__ Y) {
    extern __shared__ __align__(16) char sm[];
    const int m0 = blockIdx.y * 128;
    const int n0 = blockIdx.x * 128;

    float acc[4][4][4];
    gemm_core<1>(o16, wo16, wo16, smem_u32(sm), m0, n0, acc);

    const int lane = threadIdx.x & 31;
    const int wid  = threadIdx.x >> 5;
    const int wm   = wid & 1, wn = wid >> 1;
    const int g  = lane >> 2;
    const int c2 = (lane & 3) * 2;
#pragma unroll
    for (int mi = 0; mi < 4; mi++) {
#pragma unroll
        for (int ni = 0; ni < 4; ni++) {
            int row = m0 + wm * 64 + mi * 16 + g;
            int col = n0 + wn * 32 + ni * 8 + c2;
            float2 v0 = {acc[mi][ni][0], acc[mi][ni][1]};
            float2 v1 = {acc[mi][ni][2], acc[mi][ni][3]};
            *(float2*)(Y + (size_t)row * DM + col)       = v0;
            *(float2*)(Y + (size_t)(row + 8) * DM + col) = v1;
        }
    }
}

// ===========================================================================
// Flash attention v9: QK 1-MMA, PV 1-MMA; K/V DOUBLE-BUFFERED so each k-tile
// iteration needs exactly ONE __syncthreads + ONE cp.async wait.
// 128 threads / 64 q-rows, 4 CTAs/SM.
// ===========================================================================
#define QROW_B 144
#define FT     9216
#define FQ     0
#define FK(s)  ((uint32_t)(1 + (s)) * FT)
#define FV(s)  ((uint32_t)(3 + (s)) * FT)
#define FSMEM  (5 * FT)                  // 46080

__global__ __launch_bounds__(128, 4)
void flash_v9(const char* Q16, const char* K16, const char* V16,
              uint32_t* O16) {
    extern __shared__ __align__(16) char fsm[];
    const uint32_t sb = smem_u32(fsm);

    const int t    = threadIdx.x;
    const int lane = t & 31;
    const int wid  = t >> 5;
    const int b    = blockIdx.z;
    const int h    = blockIdx.y;
    const int q0   = blockIdx.x * 64;
    const size_t rq  = (size_t)(b * SEQ + q0);
    const size_t rb0 = (size_t)(b * SEQ);
    const uint32_t hoff = (uint32_t)h * 128u;

    const int rI  = t >> 3;
    const uint32_t c16 = (uint32_t)(t & 7) << 4;

    // KV tile load helper (64 rows x 128B, 4 cp.async per thread each)
    auto load_kv = [&](int kt, int s) {
        const size_t r0 = rb0 + (size_t)kt * 64;
#pragma unroll
        for (int i = 0; i < 4; i++) {
            const int row = (i << 4) + rI;
            cpa16(sb + FK(s) + (uint32_t)row * QROW_B + c16,
                  K16 + (r0 + row) * 2048 + hoff + c16);
        }
#pragma unroll
        for (int i = 0; i < 4; i++) {
            const int row = (i << 4) + rI;
            cpa16(sb + FV(s) + (uint32_t)row * QROW_B + c16,
                  V16 + (r0 + row) * 2048 + hoff + c16);
        }
    };

    // Prologue: Q + KV(0) in one group
#pragma unroll
    for (int i = 0; i < 4; i++) {
        const int row = (i << 4) + rI;
        cpa16(sb + FQ + (uint32_t)row * QROW_B + c16,
              Q16 + (rq + row) * 2048 + hoff + c16);
    }
    load_kv(0, 0);
    CP_COMMIT;

    const int r8  = lane & 7;
    const int sel = lane >> 3;
    const uint32_t aOff = (uint32_t)(wid * 16 + (sel & 1) * 8 + r8) * QROW_B
                        + (uint32_t)((sel >> 1) * 16);
    const uint32_t bOff = (uint32_t)((sel >> 1) * 8 + r8) * QROW_B
                        + (uint32_t)((sel & 1) * 16);
    const uint32_t vOff = (uint32_t)((sel & 1) * 8 + r8) * QROW_B
                        + (uint32_t)((sel >> 1) * 16);

    float m_s[2] = {-1.0e30f, -1.0e30f};
    float l_s[2] = {0.f, 0.f};
    float o[8][4];
#pragma unroll
    for (int j = 0; j < 8; j++)
#pragma unroll
        for (int e = 0; e < 4; e++) o[j][e] = 0.f;

    const int NT = SEQ / 64;
    for (int kt = 0; kt < NT; kt++) {
        const int s = kt & 1;

        CP_WAIT0;               // KV(kt) arrived (only outstanding group)
        __syncthreads();        // all warps done with buffer s from iter kt-2

        if (kt + 1 < NT) {      // prefetch KV(kt+1) into s^1; covered by compute
            load_kv(kt + 1, s ^ 1);
            CP_COMMIT;
        }

        // ---- S = Q @ K^T (1-MMA) ----
        float sc[8][4];
#pragma unroll
        for (int j = 0; j < 8; j++)
#pragma unroll
            for (int e = 0; e < 4; e++) sc[j][e] = 0.f;

#pragma unroll
        for (int kc = 0; kc < 4; kc++) {
            const uint32_t kb = (uint32_t)kc * 32;
            uint32_t aq[4];
            ldsm4(aq, sb + FQ + aOff + kb);
#pragma unroll
            for (int j = 0; j < 4; j++) {
                uint32_t bk[4];
                ldsm4(bk, sb + FK(s) + bOff + (uint32_t)(j * 16) * QROW_B + kb);
                MMA_F16(sc[2 * j],     aq, bk[0], bk[1]);
                MMA_F16(sc[2 * j + 1], aq, bk[2], bk[3]);
            }
        }

        // ---- online softmax (log2 domain) ----
        float mx0 = sc[0][0], mx1 = sc[0][2];
#pragma unroll
        for (int j = 0; j < 8; j++) {
            mx0 = fmaxf(mx0, fmaxf(sc[j][0], sc[j][1]));
            mx1 = fmaxf(mx1, fmaxf(sc[j][2], sc[j][3]));
        }
        mx0 = fmaxf(mx0, __shfl_xor_sync(0xffffffffu, mx0, 1));
        mx0 = fmaxf(mx0, __shfl_xor_sync(0xffffffffu, mx0, 2));
        mx1 = fmaxf(mx1, __shfl_xor_sync(0xffffffffu, mx1, 1));
        mx1 = fmaxf(mx1, __shfl_xor_sync(0xffffffffu, mx1, 2));

        const float mn0 = fmaxf(m_s[0], mx0);
        const float mn1 = fmaxf(m_s[1], mx1);
        const float al0 = fexp2(m_s[0] - mn0);
        const float al1 = fexp2(m_s[1] - mn1);
        m_s[0] = mn0; m_s[1] = mn1;

        float sum0 = 0.f, sum1 = 0.f;
#pragma unroll
        for (int j = 0; j < 8; j++) {
            sc[j][0] = fexp2(sc[j][0] - mn0);
            sc[j][1] = fexp2(sc[j][1] - mn0);
            sc[j][2] = fexp2(sc[j][2] - mn1);
            sc[j][3] = fexp2(sc[j][3] - mn1);
            sum0 += sc[j][0] + sc[j][1];
            sum1 += sc[j][2] + sc[j][3];
        }
        sum0 += __shfl_xor_sync(0xffffffffu, sum0, 1);
        sum0 += __shfl_xor_sync(0xffffffffu, sum0, 2);
        sum1 += __shfl_xor_sync(0xffffffffu, sum1, 1);
        sum1 += __shfl_xor_sync(0xffffffffu, sum1, 2);
        l_s[0] = l_s[0] * al0 + sum0;
        l_s[1] = l_s[1] * al1 + sum1;

#pragma unroll
        for (int j = 0; j < 8; j++) {
            o[j][0] *= al0; o[j][1] *= al0;
            o[j][2] *= al1; o[j][3] *= al1;
        }

        // ---- PV (1-MMA) ----
#pragma unroll
        for (int kk = 0; kk < 4; kk++) {
            float* s0 = sc[2 * kk];
            float* s1 = sc[2 * kk + 1];
            uint32_t pa[4];
            pa[0] = pack_h2(s0[0], s0[1]);
            pa[1] = pack_h2(s0[2], s0[3]);
            pa[2] = pack_h2(s1[0], s1[1]);
            pa[3] = pack_h2(s1[2], s1[3]);
            const uint32_t rowk = (uint32_t)(kk * 16) * QROW_B;
#pragma unroll
            for (int j = 0; j < 4; j++) {
                uint32_t vv[4];
                ldsm4t(vv, sb + FV(s) + vOff + rowk + (uint32_t)(j * 32));
                MMA_F16(o[2 * j],     pa, vv[0], vv[1]);
                MMA_F16(o[2 * j + 1], pa, vv[2], vv[3]);
            }
        }
    }

    // ---- epilogue: O plain fp16 ----
    const int g  = lane >> 2;
    const int c2 = (lane & 3) * 2;
    const float inv0 = 1.f / l_s[0];
    const float inv1 = 1.f / l_s[1];
    const size_t row0 = rq + (size_t)(wid * 16 + g);
#pragma unroll
    for (int j = 0; j < 8; j++) {
        size_t i0 = (row0 * DM + h * DH + j * 8 + c2) >> 1;
        size_t i1 = ((row0 + 8) * DM + h * DH + j * 8 + c2) >> 1;
        O16[i0] = pack_h2(o[j][0] * inv0, o[j][1] * inv0);
        O16[i1] = pack_h2(o[j][2] * inv1, o[j][3] * inv1);
    }
}

// ---------------------------------------------------------------------------
// Launch
// ---------------------------------------------------------------------------
extern "C" void kernel_launch(void* const* d_in, const int* in_sizes, int n_in,
                              void* d_out, int out_size) {
    const float* x   = (const float*)d_in[0];
    const float* src = (const float*)d_in[1];
    const float* Wq  = (const float*)d_in[2];
    const float* Wk  = (const float*)d_in[3];
    const float* Wv  = (const float*)d_in[4];
    const float* Wo  = (const float*)d_in[5];
    float* out = (float*)d_out;

    void *x16, *s16, *q16, *k16, *v16, *o16;
    void *wqh, *wql, *wkh, *wkl, *wv16, *wo16;
    cudaGetSymbolAddress(&x16, g_x16);
    cudaGetSymbolAddress(&s16, g_s16);
    cudaGetSymbolAddress(&q16, g_q16);
    cudaGetSymbolAddress(&k16, g_k16);
    cudaGetSymbolAddress(&v16, g_v16);
    cudaGetSymbolAddress(&o16, g_o16);
    cudaGetSymbolAddress(&wqh, g_wqh); cudaGetSymbolAddress(&wql, g_wql);
    cudaGetSymbolAddress(&wkh, g_wkh); cudaGetSymbolAddress(&wkl, g_wkl);
    cudaGetSymbolAddress(&wv16, g_wv16);
    cudaGetSymbolAddress(&wo16, g_wo16);

    cudaFuncSetAttribute(gemm_qkv5, cudaFuncAttributeMaxDynamicSharedMemorySize, GSMEM2);
    cudaFuncSetAttribute(gemm_out5, cudaFuncAttributeMaxDynamicSharedMemorySize, GSMEM1);
    cudaFuncSetAttribute(flash_v9, cudaFuncAttributeMaxDynamicSharedMemorySize, FSMEM);

    const float qs = 0.125f * 1.4426950408889634f;

    prep_all<<<(N4TOT + 255) / 256, 256>>>(
        (const float4*)x, (const float4*)src, (const float4*)Wq,
        (const float4*)Wk, (const float4*)Wv, (const float4*)Wo,
        (uint2*)x16, (uint2*)s16, (uint2*)wqh, (uint2*)wql,
        (uint2*)wkh, (uint2*)wkl, (uint2*)wv16, (uint2*)wo16, qs);

    dim3 qkvgrid(DM / 128, M_TOT / 128, 3);
    gemm_qkv5<<<qkvgrid, 256, GSMEM2>>>(
        (const char*)x16, (const char*)s16,
        (const char*)wqh, (const char*)wql, (const char*)wkh, (const char*)wkl,
        (const char*)wv16,
        (uint32_t*)q16, (uint32_t*)k16, (uint32_t*)v16);

    dim3 agrid(SEQ / 64, NH, BATCH);
    flash_v9<<<agrid, 128, FSMEM>>>(
        (const char*)q16, (const char*)k16, (const char*)v16, (uint32_t*)o16);

    dim3 ggrid(DM / 128, M_TOT / 128);
    gemm_out5<<<ggrid, 256, GSMEM1>>>(
        (const char*)o16, (const char*)wo16, out);
}

// round 13
// speedup vs baseline: 2.1486x; 1.0995x over previous
#include <cuda_runtime.h>
#include <cuda_fp16.h>
#include <cstdint>

#define DM     1024
#define NH     16
#define DH     64
#define SEQ    2048
#define BATCH  2
#define M_TOT  (BATCH * SEQ)   // 4096

// ---- fp16 scratch (ALL plain now) ----
__device__ __half g_x16[(size_t)M_TOT * DM];
__device__ __half g_s16[(size_t)M_TOT * DM];
__device__ __half g_q16[(size_t)M_TOT * DM];          // Q (pre-scaled)
__device__ __half g_k16[(size_t)M_TOT * DM];
__device__ __half g_v16[(size_t)M_TOT * DM];
__device__ __half g_o16[(size_t)M_TOT * DM];
__device__ __half g_wq16[DM * DM];
__device__ __half g_wk16[DM * DM];
__device__ __half g_wv16[DM * DM];
__device__ __half g_wo16[DM * DM];

// ===========================================================================
// Helpers
// ===========================================================================
__device__ __forceinline__ uint32_t smem_u32(const void* p) {
    uint32_t a;
    asm("{ .reg .u64 t; cvta.to.shared.u64 t, %1; cvt.u32.u64 %0, t; }"
        : "=r"(a) : "l"(p));
    return a;
}
__device__ __forceinline__ void ldsm4(uint32_t* r, uint32_t addr) {
    asm volatile("ldmatrix.sync.aligned.m8n8.x4.shared.b16 {%0,%1,%2,%3}, [%4];"
                 : "=r"(r[0]), "=r"(r[1]), "=r"(r[2]), "=r"(r[3]) : "r"(addr));
}
__device__ __forceinline__ void ldsm4t(uint32_t* r, uint32_t addr) {
    asm volatile("ldmatrix.sync.aligned.m8n8.x4.trans.shared.b16 {%0,%1,%2,%3}, [%4];"
                 : "=r"(r[0]), "=r"(r[1]), "=r"(r[2]), "=r"(r[3]) : "r"(addr));
}
__device__ __forceinline__ void cpa16(uint32_t saddr, const void* gaddr) {
    asm volatile("cp.async.cg.shared.global [%0], [%1], 16;"
                 :: "r"(saddr), "l"(gaddr) : "memory");
}
#define CP_COMMIT asm volatile("cp.async.commit_group;" ::: "memory")
#define CP_WAIT0  asm volatile("cp.async.wait_group 0;" ::: "memory")
#define CP_WAIT1  asm volatile("cp.async.wait_group 1;" ::: "memory")

#define MMA_F16(d, a, b0, b1) \
    asm volatile("mma.sync.aligned.m16n8k16.row.col.f32.f16.f16.f32 " \
                 "{%0,%1,%2,%3},{%4,%5,%6,%7},{%8,%9},{%0,%1,%2,%3};" \
                 : "+f"((d)[0]), "+f"((d)[1]), "+f"((d)[2]), "+f"((d)[3]) \
                 : "r"((a)[0]), "r"((a)[1]), "r"((a)[2]), "r"((a)[3]), \
                   "r"(b0), "r"(b1))

__device__ __forceinline__ uint32_t pack_h2(float x, float y) {
    __half2 p = __floats2half2_rn(x, y);
    return *reinterpret_cast<uint32_t*>(&p);
}
__device__ __forceinline__ float fexp2(float x) {
    x = fmaxf(x, -126.0f);
    float z = x + 12582912.0f;
    float f = x - (z - 12582912.0f);
    float p = 0.0013333558f;
    p = fmaf(p, f, 0.0096181291f);
    p = fmaf(p, f, 0.0555041087f);
    p = fmaf(p, f, 0.2402265069f);
    p = fmaf(p, f, 0.6931471806f);
    p = fmaf(p, f, 1.0f);
    return __uint_as_float(__float_as_uint(p) + (__float_as_uint(z) << 23));
}

// ===========================================================================
// Fused prep: all six fp32 -> plain fp16 conversions in ONE launch.
// Regions (float4 units): x | src | Wq(scaled) | Wk | Wv | Wo
// ===========================================================================
#define N4X (M_TOT * DM / 4)      // 1048576
#define N4W (DM * DM / 4)         // 262144
#define N4TOT (2 * N4X + 4 * N4W) // 3145728

__global__ __launch_bounds__(256)
void prep_all(const float4* __restrict__ x,   const float4* __restrict__ src,
              const float4* __restrict__ Wq,  const float4* __restrict__ Wk,
              const float4* __restrict__ Wv,  const float4* __restrict__ Wo,
              uint2* __restrict__ x16,  uint2* __restrict__ s16,
              uint2* __restrict__ wq16, uint2* __restrict__ wk16,
              uint2* __restrict__ wv16, uint2* __restrict__ wo16,
              float qs) {
    int i = blockIdx.x * blockDim.x + threadIdx.x;
    if (i >= N4TOT) return;

    const float4* src_p;
    uint2* dst_p;
    int j;
    float scale = 1.f;
    if (i < N4X)                { src_p = x;  dst_p = x16;  j = i; }
    else if (i < 2 * N4X)       { src_p = src; dst_p = s16; j = i - N4X; }
    else {
        j = i - 2 * N4X;
        if (j < N4W)            { src_p = Wq; dst_p = wq16; scale = qs; }
        else if (j < 2 * N4W)   { src_p = Wk; dst_p = wk16; j -= N4W; }
        else if (j < 3 * N4W)   { src_p = Wv; dst_p = wv16; j -= 2 * N4W; }
        else                    { src_p = Wo; dst_p = wo16; j -= 3 * N4W; }
    }
    float4 v = src_p[j];
    v.x *= scale; v.y *= scale; v.z *= scale; v.w *= scale;
    dst_p[j] = make_uint2(pack_h2(v.x, v.y), pack_h2(v.z, v.w));
}

// ===========================================================================
// fp16 1-MMA GEMM core: Y = A @ B^T, 128x128 tile, KC=32,
// THREE-stage cp.async pipeline (covers L2 latency).
// ===========================================================================
#define LDT2 80
#define TILE_BYTES (128 * LDT2)          // 10240
#define STG1 (2 * TILE_BYTES)            // A, B
#define GSMEM (3 * STG1)                 // 61440

__device__ __forceinline__ void g_issue1(uint32_t ss, const char* A,
                                         const char* B, int m0, int n0,
                                         uint32_t k0b, int t) {
#pragma unroll
    for (int i = 0; i < 4; i++) {
        const char* g = (i < 2) ? A : B;
        const uint32_t slot = (uint32_t)(i >> 1);
        const int r0 = (i < 2) ? m0 : n0;
        const int row = ((i & 1) << 6) + (t >> 2);
        const uint32_t c16 = (uint32_t)(t & 3) << 4;
        cpa16(ss + slot * (uint32_t)TILE_BYTES + (uint32_t)row * LDT2 + c16,
              g + (size_t)(r0 + row) * 2048 + k0b + c16);
    }
}

__device__ __forceinline__ void gemm_core1(const char* A, const char* B,
                                           uint32_t sbase, int m0, int n0,
                                           float (&acc)[4][4][4]) {
    const int t    = threadIdx.x;
    const int lane = t & 31;
    const int wid  = t >> 5;
    const int wm   = wid & 1;
    const int wn   = wid >> 1;

#pragma unroll
    for (int mi = 0; mi < 4; mi++)
#pragma unroll
        for (int ni = 0; ni < 4; ni++)
#pragma unroll
            for (int e = 0; e < 4; e++) acc[mi][ni][e] = 0.f;

    const int r8  = lane & 7;
    const int sel = lane >> 3;
    const uint32_t aRowOff = (uint32_t)(wm * 64 + (sel & 1) * 8 + r8) * LDT2
                           + (uint32_t)((sel >> 1) * 8) * 2;
    const uint32_t bRowOff = (uint32_t)(wn * 32 + (sel >> 1) * 8 + r8) * LDT2
                           + (uint32_t)((sel & 1) * 8) * 2;

    auto compute = [&](uint32_t sb) {
        const uint32_t sA = sb;
        const uint32_t sB = sb + TILE_BYTES;
#pragma unroll
        for (int ks = 0; ks < 2; ks++) {
            const uint32_t kb = (uint32_t)ks * 32;
            uint32_t ah[4][4];
#pragma unroll
            for (int mi = 0; mi < 4; mi++)
                ldsm4(ah[mi], sA + aRowOff + (uint32_t)(mi * 16) * LDT2 + kb);
            uint32_t bh[2][4];
#pragma unroll
            for (int np = 0; np < 2; np++)
                ldsm4(bh[np], sB + bRowOff + (uint32_t)(np * 16) * LDT2 + kb);
#pragma unroll
            for (int mi = 0; mi < 4; mi++)
#pragma unroll
                for (int ni = 0; ni < 4; ni++)
                    MMA_F16(acc[mi][ni], ah[mi],
                            bh[ni >> 1][(ni & 1) * 2],
                            bh[ni >> 1][(ni & 1) * 2 + 1]);
        }
    };

    // 3-stage prologue: chunks 0 and 1 in flight
    g_issue1(sbase,            A, B, m0, n0, 0u,  t);  CP_COMMIT;
    g_issue1(sbase + STG1,     A, B, m0, n0, 64u, t);  CP_COMMIT;

    const int NCHUNK = DM / 32;   // 32
    uint32_t soff[3] = {0u, (uint32_t)STG1, (uint32_t)(2 * STG1)};
    int s = 0;
    for (int chunk = 0; chunk < NCHUNK; chunk++) {
        if (chunk + 1 < NCHUNK) { CP_WAIT1; } else { CP_WAIT0; }
        __syncthreads();
        if (chunk + 2 < NCHUNK) {
            int s2 = s + 2; if (s2 >= 3) s2 -= 3;
            g_issue1(sbase + soff[s2], A, B, m0, n0,
                     (uint32_t)(chunk + 2) * 64, t);
            CP_COMMIT;
        }
        compute(sbase + soff[s]);
        if (++s == 3) s = 0;
    }
}

// QKV projections: uniform 1-MMA, z selects (A, B, Y). Plain fp16 out.
__global__ __launch_bounds__(256, 2)
void gemm_qkv6(const char* x16, const char* s16,
               const char* wq16, const char* wk16, const char* wv16,
               uint32_t* q16, uint32_t* k16, uint32_t* v16) {
    extern __shared__ __align__(16) char sm[];
    const int z  = blockIdx.z;
    const int m0 = blockIdx.y * 128;
    const int n0 = blockIdx.x * 128;
    const char* A = (z == 0) ? x16 : s16;
    const char* B = (z == 0) ? wq16 : (z == 1 ? wk16 : wv16);
    uint32_t* Y   = (z == 0) ? q16 : (z == 1 ? k16 : v16);

    float acc[4][4][4];
    gemm_core1(A, B, smem_u32(sm), m0, n0, acc);

    const int lane = threadIdx.x & 31;
    const int wid  = threadIdx.x >> 5;
    const int wm   = wid & 1, wn = wid >> 1;
    const int g  = lane >> 2;
    const int c2 = (lane & 3) * 2;
#pragma unroll
    for (int mi = 0; mi < 4; mi++) {
#pragma unroll
        for (int ni = 0; ni < 4; ni++) {
            int row = m0 + wm * 64 + mi * 16 + g;
            int col = n0 + wn * 32 + ni * 8 + c2;
            Y[((size_t)row * DM + col) >> 1]       = pack_h2(acc[mi][ni][0], acc[mi][ni][1]);
            Y[((size_t)(row + 8) * DM + col) >> 1] = pack_h2(acc[mi][ni][2], acc[mi][ni][3]);
        }
    }
}

// Output projection: 1-MMA, fp32 epilogue.
__global__ __launch_bounds__(256, 2)
void gemm_out6(const char* o16, const char* wo16, float* __restrict__ Y) {
    extern __shared__ __align__(16) char sm[];
    const int m0 = blockIdx.y * 128;
    const int n0 = blockIdx.x * 128;

    float acc[4][4][4];
    gemm_core1(o16, wo16, smem_u32(sm), m0, n0, acc);

    const int lane = threadIdx.x & 31;
    const int wid  = threadIdx.x >> 5;
    const int wm   = wid & 1, wn = wid >> 1;
    const int g  = lane >> 2;
    const int c2 = (lane & 3) * 2;
#pragma unroll
    for (int mi = 0; mi < 4; mi++) {
#pragma unroll
        for (int ni = 0; ni < 4; ni++) {
            int row = m0 + wm * 64 + mi * 16 + g;
            int col = n0 + wn * 32 + ni * 8 + c2;
            float2 v0 = {acc[mi][ni][0], acc[mi][ni][1]};
            float2 v1 = {acc[mi][ni][2], acc[mi][ni][3]};
            *(float2*)(Y + (size_t)row * DM + col)       = v0;
            *(float2*)(Y + (size_t)(row + 8) * DM + col) = v1;
        }
    }
}

// ===========================================================================
// Flash attention v9 (unchanged from R12): QK 1-MMA, PV 1-MMA,
// K/V double-buffered, one sync + one wait per k-tile. 4 CTAs/SM.
// ===========================================================================
#define QROW_B 144
#define FT     9216
#define FQ     0
#define FK(s)  ((uint32_t)(1 + (s)) * FT)
#define FV(s)  ((uint32_t)(3 + (s)) * FT)
#define FSMEM  (5 * FT)                  // 46080

__global__ __launch_bounds__(128, 4)
void flash_v9(const char* Q16, const char* K16, const char* V16,
              uint32_t* O16) {
    extern __shared__ __align__(16) char fsm[];
    const uint32_t sb = smem_u32(fsm);

    const int t    = threadIdx.x;
    const int lane = t & 31;
    const int wid  = t >> 5;
    const int b    = blockIdx.z;
    const int h    = blockIdx.y;
    const int q0   = blockIdx.x * 64;
    const size_t rq  = (size_t)(b * SEQ + q0);
    const size_t rb0 = (size_t)(b * SEQ);
    const uint32_t hoff = (uint32_t)h * 128u;

    const int rI  = t >> 3;
    const uint32_t c16 = (uint32_t)(t & 7) << 4;

    auto load_kv = [&](int kt, int s) {
        const size_t r0 = rb0 + (size_t)kt * 64;
#pragma unroll
        for (int i = 0; i < 4; i++) {
            const int row = (i << 4) + rI;
            cpa16(sb + FK(s) + (uint32_t)row * QROW_B + c16,
                  K16 + (r0 + row) * 2048 + hoff + c16);
        }
#pragma unroll
        for (int i = 0; i < 4; i++) {
            const int row = (i << 4) + rI;
            cpa16(sb + FV(s) + (uint32_t)row * QROW_B + c16,
                  V16 + (r0 + row) * 2048 + hoff + c16);
        }
    };

#pragma unroll
    for (int i = 0; i < 4; i++) {
        const int row = (i << 4) + rI;
        cpa16(sb + FQ + (uint32_t)row * QROW_B + c16,
              Q16 + (rq + row) * 2048 + hoff + c16);
    }
    load_kv(0, 0);
    CP_COMMIT;

    const int r8  = lane & 7;
    const int sel = lane >> 3;
    const uint32_t aOff = (uint32_t)(wid * 16 + (sel & 1) * 8 + r8) * QROW_B
                        + (uint32_t)((sel >> 1) * 16);
    const uint32_t bOff = (uint32_t)((sel >> 1) * 8 + r8) * QROW_B
                        + (uint32_t)((sel & 1) * 16);
    const uint32_t vOff = (uint32_t)((sel & 1) * 8 + r8) * QROW_B
                        + (uint32_t)((sel >> 1) * 16);

    float m_s[2] = {-1.0e30f, -1.0e30f};
    float l_s[2] = {0.f, 0.f};
    float o[8][4];
#pragma unroll
    for (int j = 0; j < 8; j++)
#pragma unroll
        for (int e = 0; e < 4; e++) o[j][e] = 0.f;

    const int NT = SEQ / 64;
    for (int kt = 0; kt < NT; kt++) {
        const int s = kt & 1;

        CP_WAIT0;
        __syncthreads();

        if (kt + 1 < NT) {
            load_kv(kt + 1, s ^ 1);
            CP_COMMIT;
        }

        float sc[8][4];
#pragma unroll
        for (int j = 0; j < 8; j++)
#pragma unroll
            for (int e = 0; e < 4; e++) sc[j][e] = 0.f;

#pragma unroll
        for (int kc = 0; kc < 4; kc++) {
            const uint32_t kb = (uint32_t)kc * 32;
            uint32_t aq[4];
            ldsm4(aq, sb + FQ + aOff + kb);
#pragma unroll
            for (int j = 0; j < 4; j++) {
                uint32_t bk[4];
                ldsm4(bk, sb + FK(s) + bOff + (uint32_t)(j * 16) * QROW_B + kb);
                MMA_F16(sc[2 * j],     aq, bk[0], bk[1]);
                MMA_F16(sc[2 * j + 1], aq, bk[2], bk[3]);
            }
        }

        float mx0 = sc[0][0], mx1 = sc[0][2];
#pragma unroll
        for (int j = 0; j < 8; j++) {
            mx0 = fmaxf(mx0, fmaxf(sc[j][0], sc[j][1]));
            mx1 = fmaxf(mx1, fmaxf(sc[j][2], sc[j][3]));
        }
        mx0 = fmaxf(mx0, __shfl_xor_sync(0xffffffffu, mx0, 1));
        mx0 = fmaxf(mx0, __shfl_xor_sync(0xffffffffu, mx0, 2));
        mx1 = fmaxf(mx1, __shfl_xor_sync(0xffffffffu, mx1, 1));
        mx1 = fmaxf(mx1, __shfl_xor_sync(0xffffffffu, mx1, 2));

        const float mn0 = fmaxf(m_s[0], mx0);
        const float mn1 = fmaxf(m_s[1], mx1);
        const float al0 = fexp2(m_s[0] - mn0);
        const float al1 = fexp2(m_s[1] - mn1);
        m_s[0] = mn0; m_s[1] = mn1;

        float sum0 = 0.f, sum1 = 0.f;
#pragma unroll
        for (int j = 0; j < 8; j++) {
            sc[j][0] = fexp2(sc[j][0] - mn0);
            sc[j][1] = fexp2(sc[j][1] - mn0);
            sc[j][2] = fexp2(sc[j][2] - mn1);
            sc[j][3] = fexp2(sc[j][3] - mn1);
            sum0 += sc[j][0] + sc[j][1];
            sum1 += sc[j][2] + sc[j][3];
        }
        sum0 += __shfl_xor_sync(0xffffffffu, sum0, 1);
        sum0 += __shfl_xor_sync(0xffffffffu, sum0, 2);
        sum1 += __shfl_xor_sync(0xffffffffu, sum1, 1);
        sum1 += __shfl_xor_sync(0xffffffffu, sum1, 2);
        l_s[0] = l_s[0] * al0 + sum0;
        l_s[1] = l_s[1] * al1 + sum1;

#pragma unroll
        for (int j = 0; j < 8; j++) {
            o[j][0] *= al0; o[j][1] *= al0;
            o[j][2] *= al1; o[j][3] *= al1;
        }

#pragma unroll
        for (int kk = 0; kk < 4; kk++) {
            float* s0 = sc[2 * kk];
            float* s1 = sc[2 * kk + 1];
            uint32_t pa[4];
            pa[0] = pack_h2(s0[0], s0[1]);
            pa[1] = pack_h2(s0[2], s0[3]);
            pa[2] = pack_h2(s1[0], s1[1]);
            pa[3] = pack_h2(s1[2], s1[3]);
            const uint32_t rowk = (uint32_t)(kk * 16) * QROW_B;
#pragma unroll
            for (int j = 0; j < 4; j++) {
                uint32_t vv[4];
                ldsm4t(vv, sb + FV(s) + vOff + rowk + (uint32_t)(j * 32));
                MMA_F16(o[2 * j],     pa, vv[0], vv[1]);
                MMA_F16(o[2 * j + 1], pa, vv[2], vv[3]);
            }
        }
    }

    const int g  = lane >> 2;
    const int c2 = (lane & 3) * 2;
    const float inv0 = 1.f / l_s[0];
    const float inv1 = 1.f / l_s[1];
    const size_t row0 = rq + (size_t)(wid * 16 + g);
#pragma unroll
    for (int j = 0; j < 8; j++) {
        size_t i0 = (row0 * DM + h * DH + j * 8 + c2) >> 1;
        size_t i1 = ((row0 + 8) * DM + h * DH + j * 8 + c2) >> 1;
        O16[i0] = pack_h2(o[j][0] * inv0, o[j][1] * inv0);
        O16[i1] = pack_h2(o[j][2] * inv1, o[j][3] * inv1);
    }
}

// ---------------------------------------------------------------------------
// Launch
// ---------------------------------------------------------------------------
extern "C" void kernel_launch(void* const* d_in, const int* in_sizes, int n_in,
                              void* d_out, int out_size) {
    const float* x   = (const float*)d_in[0];
    const float* src = (const float*)d_in[1];
    const float* Wq  = (const float*)d_in[2];
    const float* Wk  = (const float*)d_in[3];
    const float* Wv  = (const float*)d_in[4];
    const float* Wo  = (const float*)d_in[5];
    float* out = (float*)d_out;

    void *x16, *s16, *q16, *k16, *v16, *o16;
    void *wq16, *wk16, *wv16, *wo16;
    cudaGetSymbolAddress(&x16, g_x16);
    cudaGetSymbolAddress(&s16, g_s16);
    cudaGetSymbolAddress(&q16, g_q16);
    cudaGetSymbolAddress(&k16, g_k16);
    cudaGetSymbolAddress(&v16, g_v16);
    cudaGetSymbolAddress(&o16, g_o16);
    cudaGetSymbolAddress(&wq16, g_wq16);
    cudaGetSymbolAddress(&wk16, g_wk16);
    cudaGetSymbolAddress(&wv16, g_wv16);
    cudaGetSymbolAddress(&wo16, g_wo16);

    cudaFuncSetAttribute(gemm_qkv6, cudaFuncAttributeMaxDynamicSharedMemorySize, GSMEM);
    cudaFuncSetAttribute(gemm_out6, cudaFuncAttributeMaxDynamicSharedMemorySize, GSMEM);
    cudaFuncSetAttribute(flash_v9,  cudaFuncAttributeMaxDynamicSharedMemorySize, FSMEM);

    const float qs = 0.125f * 1.4426950408889634f;

    prep_all<<<(N4TOT + 255) / 256, 256>>>(
        (const float4*)x, (const float4*)src, (const float4*)Wq,
        (const float4*)Wk, (const float4*)Wv, (const float4*)Wo,
        (uint2*)x16, (uint2*)s16, (uint2*)wq16, (uint2*)wk16,
        (uint2*)wv16, (uint2*)wo16, qs);

    dim3 qkvgrid(DM / 128, M_TOT / 128, 3);
    gemm_qkv6<<<qkvgrid, 256, GSMEM>>>(
        (const char*)x16, (const char*)s16,
        (const char*)wq16, (const char*)wk16, (const char*)wv16,
        (uint32_t*)q16, (uint32_t*)k16, (uint32_t*)v16);

    dim3 agrid(SEQ / 64, NH, BATCH);
    flash_v9<<<agrid, 128, FSMEM>>>(
        (const char*)q16, (const char*)k16, (const char*)v16, (uint32_t*)o16);

    dim3 ggrid(DM / 128, M_TOT / 128);
    gemm_out6<<<ggrid, 256, GSMEM>>>(
        (const char*)o16, (const char*)wo16, out);
}